// round 1
// baseline (speedup 1.0000x reference)
#include <cuda_runtime.h>
#include <math.h>

// Problem constants
#define Bq   2
#define Sq   2048
#define Hd   2048
#define Id   4096
#define NE   8
#define TOPK 2
#define T    (Bq * Sq)          // 4096 tokens

// GEMM tiling
#define TM 128
#define TN 64
#define TK 16
#define APAD 132                // padded A-tile row (bank-conflict mitigation)

// ---------------------------------------------------------------------------
// Device scratch (static: no allocations allowed)
// ---------------------------------------------------------------------------
__device__ int   g_count[NE];
__device__ int   g_tok[NE][T];
__device__ float g_wt[NE][T];
// GU scratch: worst case one expert holds all T tokens -> [NE][T][Id] fp32
__device__ float g_gu[NE][T][Id];   // 8*4096*4096*4 = 536 MB (bss)

// ---------------------------------------------------------------------------
__global__ void zero_counts_kernel() {
    if (threadIdx.x < NE) g_count[threadIdx.x] = 0;
}

__device__ __forceinline__ float gelu_tanh(float v) {
    const float c = 0.7978845608028654f;  // sqrt(2/pi)
    float inner = c * (v + 0.044715f * v * v * v);
    return 0.5f * v * (1.0f + tanhf(inner));
}

// ---------------------------------------------------------------------------
// Router: logits = x @ gate_w, top-2 + softmax, bucket append.
// One warp per token. Writes router_logits to out_logits[t*NE + e].
// ---------------------------------------------------------------------------
__global__ void router_kernel(const float* __restrict__ x,
                              const float* __restrict__ gw,
                              float* __restrict__ out_logits) {
    int warp = (blockIdx.x * blockDim.x + threadIdx.x) >> 5;
    int lane = threadIdx.x & 31;
    if (warp >= T) return;

    const float* xr = x + (size_t)warp * Hd;
    float acc[NE];
#pragma unroll
    for (int e = 0; e < NE; e++) acc[e] = 0.0f;

    for (int h = lane; h < Hd; h += 32) {
        float xv = xr[h];
        const float* g = gw + (size_t)h * NE;
#pragma unroll
        for (int e = 0; e < NE; e++) acc[e] = fmaf(xv, g[e], acc[e]);
    }
#pragma unroll
    for (int e = 0; e < NE; e++) {
#pragma unroll
        for (int off = 16; off; off >>= 1)
            acc[e] += __shfl_xor_sync(0xffffffffu, acc[e], off);
    }

    if (lane == 0) {
        // write router logits
        float* dst = out_logits + (size_t)warp * NE;
#pragma unroll
        for (int e = 0; e < NE; e++) dst[e] = acc[e];

        // top-2 (first occurrence wins ties, matching jax.lax.top_k)
        float l0 = -3.4e38f; int e0 = 0;
#pragma unroll
        for (int e = 0; e < NE; e++)
            if (acc[e] > l0) { l0 = acc[e]; e0 = e; }
        float l1 = -3.4e38f; int e1 = 0;
#pragma unroll
        for (int e = 0; e < NE; e++)
            if (e != e0 && acc[e] > l1) { l1 = acc[e]; e1 = e; }

        // softmax over [l0, l1]
        float w1 = __expf(l1 - l0);
        float inv = 1.0f / (1.0f + w1);
        float w0 = inv;
        w1 *= inv;

        int p0 = atomicAdd(&g_count[e0], 1);
        g_tok[e0][p0] = warp; g_wt[e0][p0] = w0;
        int p1 = atomicAdd(&g_count[e1], 1);
        g_tok[e1][p1] = warp; g_wt[e1][p1] = w1;
    }
}

// ---------------------------------------------------------------------------
// Fused gate+up GEMM with row gather.
// C1 = Xe @ gate_proj[e], C2 = Xe @ up_proj[e]; GU = gelu(C1) * C2
// grid: (Id/TN, T/TM, NE), 256 threads, tile 128x64x16, dual accumulators.
// ---------------------------------------------------------------------------
__global__ __launch_bounds__(256, 2)
void gateup_kernel(const float* __restrict__ x,
                   const float* __restrict__ gate_proj,
                   const float* __restrict__ up_proj) {
    int e  = blockIdx.z;
    int ne = g_count[e];
    int m0 = blockIdx.y * TM;
    if (m0 >= ne) return;
    int n0 = blockIdx.x * TN;

    __shared__ float As[TK][APAD];
    __shared__ float Bg[TK][TN];
    __shared__ float Bu[TK][TN];
    __shared__ int   rows[TM];

    int tid = threadIdx.x;
    if (tid < TM) {
        int m = m0 + tid;
        rows[tid] = (m < ne) ? g_tok[e][m] : -1;
    }
    __syncthreads();

    const float* bg_base = gate_proj + (size_t)e * Hd * Id + n0;
    const float* bu_base = up_proj   + (size_t)e * Hd * Id + n0;

    int a_m  = tid >> 2;            // 0..63
    int a_k4 = (tid & 3) * 4;
    int b_k  = tid >> 4;            // 0..15
    int b_n4 = (tid & 15) * 4;
    int tx = tid & 15, ty = tid >> 4;

    float cg[8][4], cu[8][4];
#pragma unroll
    for (int i = 0; i < 8; i++)
#pragma unroll
        for (int j = 0; j < 4; j++) { cg[i][j] = 0.0f; cu[i][j] = 0.0f; }

    for (int k0 = 0; k0 < Hd; k0 += TK) {
#pragma unroll
        for (int r = 0; r < 2; r++) {
            int m = a_m + r * 64;
            int row = rows[m];
            float4 v = make_float4(0.f, 0.f, 0.f, 0.f);
            if (row >= 0)
                v = *(const float4*)(x + (size_t)row * Hd + k0 + a_k4);
            As[a_k4 + 0][m] = v.x; As[a_k4 + 1][m] = v.y;
            As[a_k4 + 2][m] = v.z; As[a_k4 + 3][m] = v.w;
        }
        *(float4*)&Bg[b_k][b_n4] = *(const float4*)(bg_base + (size_t)(k0 + b_k) * Id + b_n4);
        *(float4*)&Bu[b_k][b_n4] = *(const float4*)(bu_base + (size_t)(k0 + b_k) * Id + b_n4);
        __syncthreads();

#pragma unroll
        for (int k = 0; k < TK; k++) {
            float4 a0 = *(float4*)&As[k][ty * 8];
            float4 a1 = *(float4*)&As[k][ty * 8 + 4];
            float a[8] = {a0.x, a0.y, a0.z, a0.w, a1.x, a1.y, a1.z, a1.w};
            float4 bgv = *(float4*)&Bg[k][tx * 4];
            float4 buv = *(float4*)&Bu[k][tx * 4];
            float bgx[4] = {bgv.x, bgv.y, bgv.z, bgv.w};
            float bux[4] = {buv.x, buv.y, buv.z, buv.w};
#pragma unroll
            for (int i = 0; i < 8; i++) {
#pragma unroll
                for (int j = 0; j < 4; j++) {
                    cg[i][j] = fmaf(a[i], bgx[j], cg[i][j]);
                    cu[i][j] = fmaf(a[i], bux[j], cu[i][j]);
                }
            }
        }
        __syncthreads();
    }

    float* gu_row0 = &g_gu[e][0][0];
#pragma unroll
    for (int i = 0; i < 8; i++) {
        int m = m0 + ty * 8 + i;
        if (m < ne) {
            float* dst = gu_row0 + (size_t)m * Id + n0 + tx * 4;
            float4 v;
            v.x = gelu_tanh(cg[i][0]) * cu[i][0];
            v.y = gelu_tanh(cg[i][1]) * cu[i][1];
            v.z = gelu_tanh(cg[i][2]) * cu[i][2];
            v.w = gelu_tanh(cg[i][3]) * cu[i][3];
            *(float4*)dst = v;
        }
    }
}

// ---------------------------------------------------------------------------
// Down projection: C = GU_e @ down_proj[e]; out[tok] += w * C (atomic scatter)
// grid: (Hd/TN, T/TM, NE)
// ---------------------------------------------------------------------------
__global__ __launch_bounds__(256, 2)
void down_kernel(const float* __restrict__ down_proj,
                 float* __restrict__ out) {
    int e  = blockIdx.z;
    int ne = g_count[e];
    int m0 = blockIdx.y * TM;
    if (m0 >= ne) return;
    int n0 = blockIdx.x * TN;

    __shared__ float As[TK][APAD];
    __shared__ float Bs[TK][TN];

    int tid = threadIdx.x;
    int a_m  = tid >> 2;
    int a_k4 = (tid & 3) * 4;
    int b_k  = tid >> 4;
    int b_n4 = (tid & 15) * 4;
    int tx = tid & 15, ty = tid >> 4;

    const float* a_base = &g_gu[e][0][0];
    const float* b_base = down_proj + (size_t)e * Id * Hd + n0;

    float c[8][4];
#pragma unroll
    for (int i = 0; i < 8; i++)
#pragma unroll
        for (int j = 0; j < 4; j++) c[i][j] = 0.0f;

    for (int k0 = 0; k0 < Id; k0 += TK) {
#pragma unroll
        for (int r = 0; r < 2; r++) {
            int m = m0 + a_m + r * 64;
            float4 v = make_float4(0.f, 0.f, 0.f, 0.f);
            if (m < ne)
                v = *(const float4*)(a_base + (size_t)m * Id + k0 + a_k4);
            As[a_k4 + 0][a_m + r * 64] = v.x; As[a_k4 + 1][a_m + r * 64] = v.y;
            As[a_k4 + 2][a_m + r * 64] = v.z; As[a_k4 + 3][a_m + r * 64] = v.w;
        }
        *(float4*)&Bs[b_k][b_n4] = *(const float4*)(b_base + (size_t)(k0 + b_k) * Hd + b_n4);
        __syncthreads();

#pragma unroll
        for (int k = 0; k < TK; k++) {
            float4 a0 = *(float4*)&As[k][ty * 8];
            float4 a1 = *(float4*)&As[k][ty * 8 + 4];
            float a[8] = {a0.x, a0.y, a0.z, a0.w, a1.x, a1.y, a1.z, a1.w};
            float4 bv = *(float4*)&Bs[k][tx * 4];
            float b[4] = {bv.x, bv.y, bv.z, bv.w};
#pragma unroll
            for (int i = 0; i < 8; i++)
#pragma unroll
                for (int j = 0; j < 4; j++)
                    c[i][j] = fmaf(a[i], b[j], c[i][j]);
        }
        __syncthreads();
    }

#pragma unroll
    for (int i = 0; i < 8; i++) {
        int m = m0 + ty * 8 + i;
        if (m < ne) {
            int   t = g_tok[e][m];
            float w = g_wt[e][m];
            float* dst = out + (size_t)t * Hd + n0 + tx * 4;
#pragma unroll
            for (int j = 0; j < 4; j++)
                atomicAdd(&dst[j], w * c[i][j]);
        }
    }
}

// ---------------------------------------------------------------------------
extern "C" void kernel_launch(void* const* d_in, const int* in_sizes, int n_in,
                              void* d_out, int out_size) {
    const float* x         = (const float*)d_in[0];   // [B,S,H]
    const float* gate_w    = (const float*)d_in[1];   // [H,E]
    const float* gate_proj = (const float*)d_in[2];   // [E,H,I]
    const float* up_proj   = (const float*)d_in[3];   // [E,H,I]
    const float* down_proj = (const float*)d_in[4];   // [E,I,H]
    float* out = (float*)d_out;                       // [final | router_logits]

    float* out_final  = out;
    float* out_logits = out + (size_t)T * Hd;

    // zero the accumulated-output region (poisoned 0xAA by harness)
    cudaMemsetAsync(out_final, 0, (size_t)T * Hd * sizeof(float));
    zero_counts_kernel<<<1, 32>>>();

    router_kernel<<<T / 8, 256>>>(x, gate_w, out_logits);

    dim3 g3(Id / TN, T / TM, NE);
    gateup_kernel<<<g3, 256>>>(x, gate_proj, up_proj);

    dim3 g4(Hd / TN, T / TM, NE);
    down_kernel<<<g4, 256>>>(down_proj, out_final);
}

// round 3
// speedup vs baseline: 2.6972x; 2.6972x over previous
#include <cuda_runtime.h>
#include <math.h>
#include <stdint.h>

// Problem constants
#define Hd 2048
#define Id 4096
#define NE 8
#define T  4096

// GEMM tiling: CTA = 128m x 256n(combined), stage K=16, 256 threads / 8 warps
#define BM 128
#define BK 16
#define THREADS 256
#define ASTR 20                  // A smem row stride (floats): 16 + 4 pad
#define ABUF (BM * ASTR)         // 2560 floats per buffer
#define BSTR 264                 // B smem row stride: 256 + 8 pad
#define BBUF (BK * BSTR)         // 4224 floats per buffer
#define DYN_SMEM ((2 * ABUF + 2 * BBUF) * 4)

// ---------------------------------------------------------------------------
// Static device scratch
// ---------------------------------------------------------------------------
#define GU_ROWS 9216
__device__ int   g_count[NE];
__device__ int   g_segbase[NE];
__device__ int   g_tok[NE][T];
__device__ float g_wt[NE][T];
__device__ __align__(256) float g_gu[(size_t)GU_ROWS * Id];

// ---------------------------------------------------------------------------
// PTX helpers (all compute_103-legal: sm_80-era mma.sync / ldmatrix)
// ---------------------------------------------------------------------------
__device__ __forceinline__ uint32_t f2tf(float x) {
    uint32_t r; asm("cvt.rna.tf32.f32 %0, %1;" : "=r"(r) : "f"(x)); return r;
}
__device__ __forceinline__ void ldm4(uint32_t* r, uint32_t addr) {
    asm volatile("ldmatrix.sync.aligned.m8n8.x4.shared.b16 {%0,%1,%2,%3}, [%4];"
                 : "=r"(r[0]), "=r"(r[1]), "=r"(r[2]), "=r"(r[3]) : "r"(addr));
}
__device__ __forceinline__ void mma8(float* c, const uint32_t* a, uint32_t b0, uint32_t b1) {
    asm volatile("mma.sync.aligned.m16n8k8.row.col.f32.tf32.tf32.f32 "
        "{%0,%1,%2,%3}, {%4,%5,%6,%7}, {%8,%9}, {%0,%1,%2,%3};"
        : "+f"(c[0]), "+f"(c[1]), "+f"(c[2]), "+f"(c[3])
        : "r"(a[0]), "r"(a[1]), "r"(a[2]), "r"(a[3]), "r"(b0), "r"(b1));
}
__device__ __forceinline__ float gelu_tanh(float v) {
    const float c = 0.7978845608028654f;
    float inner = c * (v + 0.044715f * v * v * v);
    return 0.5f * v * (1.0f + tanhf(inner));
}

// ---------------------------------------------------------------------------
// Router + bookkeeping
// ---------------------------------------------------------------------------
__global__ void zero_counts_kernel() {
    if (threadIdx.x < NE) g_count[threadIdx.x] = 0;
}
__global__ void prefix_kernel() {
    if (threadIdx.x == 0) {
        int b = 0;
        for (int e = 0; e < NE; e++) {
            g_segbase[e] = b;
            b += ((g_count[e] + BM - 1) / BM) * BM;
        }
    }
}

__global__ void router_kernel(const float* __restrict__ x,
                              const float* __restrict__ gw,
                              float* __restrict__ out_logits) {
    int warp = (blockIdx.x * blockDim.x + threadIdx.x) >> 5;
    int lane = threadIdx.x & 31;
    if (warp >= T) return;
    const float* xr = x + (size_t)warp * Hd;
    float acc[NE];
#pragma unroll
    for (int e = 0; e < NE; e++) acc[e] = 0.0f;
    for (int h = lane; h < Hd; h += 32) {
        float xv = xr[h];
        const float* g = gw + (size_t)h * NE;
#pragma unroll
        for (int e = 0; e < NE; e++) acc[e] = fmaf(xv, g[e], acc[e]);
    }
#pragma unroll
    for (int e = 0; e < NE; e++) {
#pragma unroll
        for (int off = 16; off; off >>= 1)
            acc[e] += __shfl_xor_sync(0xffffffffu, acc[e], off);
    }
    if (lane == 0) {
        float* dst = out_logits + (size_t)warp * NE;
#pragma unroll
        for (int e = 0; e < NE; e++) dst[e] = acc[e];
        float l0 = -3.4e38f; int e0 = 0;
#pragma unroll
        for (int e = 0; e < NE; e++)
            if (acc[e] > l0) { l0 = acc[e]; e0 = e; }
        float l1 = -3.4e38f; int e1 = 0;
#pragma unroll
        for (int e = 0; e < NE; e++)
            if (e != e0 && acc[e] > l1) { l1 = acc[e]; e1 = e; }
        float w1 = __expf(l1 - l0);
        float inv = 1.0f / (1.0f + w1);
        int p0 = atomicAdd(&g_count[e0], 1);
        g_tok[e0][p0] = warp; g_wt[e0][p0] = inv;
        int p1 = atomicAdd(&g_count[e1], 1);
        g_tok[e1][p1] = warp; g_wt[e1][p1] = w1 * inv;
    }
}

// ---------------------------------------------------------------------------
// Gate+Up GEMM (mma.sync tf32): C_gate[128x128] and C_up[128x128] per CTA.
// B smem n-space: [0,128)=gate cols, [128,256)=up cols.
// ---------------------------------------------------------------------------
__global__ __launch_bounds__(THREADS, 1)
void gateup_mma(const float* __restrict__ x,
                const float* __restrict__ gp,
                const float* __restrict__ upw) {
    int e  = blockIdx.z;
    int ne = g_count[e];
    int m0 = blockIdx.x * BM;
    if (m0 >= ne) return;
    int n0 = blockIdx.y * 128;    // per-matrix n offset within Id

    extern __shared__ float smem[];
    float* As = smem;
    float* Bs = smem + 2 * ABUF;
    __shared__ int rows[BM];

    int tid = threadIdx.x;
    int lane = tid & 31, wid = tid >> 5;
    int wm = wid >> 2, wn = wid & 3;

    if (tid < BM) {
        int m = m0 + tid;
        rows[tid] = g_tok[e][m < ne ? m : (ne - 1)];
    }
    __syncthreads();

    const float* gbase = gp  + (size_t)e * Hd * Id + n0;
    const float* ubase = upw + (size_t)e * Hd * Id + n0;

    // per-warp n-column map (smem col units)
    int nmap[8];
#pragma unroll
    for (int j = 0; j < 4; j++) { nmap[j] = wn * 32 + j * 8; nmap[j + 4] = 128 + wn * 32 + j * 8; }

    // ldmatrix A lane address base
    uint32_t a_base = (uint32_t)__cvta_generic_to_shared(As)
                    + (uint32_t)((wm * 64 + (lane & 15)) * (ASTR * 4) + (lane >> 4) * 16);

    float c[4][8][4];
#pragma unroll
    for (int i = 0; i < 4; i++)
#pragma unroll
        for (int j = 0; j < 8; j++)
#pragma unroll
            for (int q = 0; q < 4; q++) c[i][j][q] = 0.0f;

    float4 pa[2], pb[4];
    const int NST = Hd / BK;

    // --- loaders ---
    auto ldg_stage = [&](int k0) {
#pragma unroll
        for (int i = 0; i < 2; i++) {
            int idx = tid + i * 256; int m = idx >> 2, ck = idx & 3;
            pa[i] = *(const float4*)(x + (size_t)rows[m] * Hd + k0 + ck * 4);
        }
#pragma unroll
        for (int i = 0; i < 4; i++) {
            int idx = tid + i * 256; int k = idx >> 6, n = (idx & 63) * 4;
            const float* src = (n < 128) ? (gbase + (size_t)(k0 + k) * Id + n)
                                         : (ubase + (size_t)(k0 + k) * Id + (n - 128));
            pb[i] = *(const float4*)src;
        }
    };
    auto sts_stage = [&](int b) {
        float* a  = As + b * ABUF;
        float* bb = Bs + b * BBUF;
#pragma unroll
        for (int i = 0; i < 2; i++) {
            int idx = tid + i * 256; int m = idx >> 2, ck = idx & 3;
            uint4 v = { f2tf(pa[i].x), f2tf(pa[i].y), f2tf(pa[i].z), f2tf(pa[i].w) };
            *(uint4*)(a + m * ASTR + ck * 4) = v;
        }
#pragma unroll
        for (int i = 0; i < 4; i++) {
            int idx = tid + i * 256; int k = idx >> 6, n = (idx & 63) * 4;
            uint4 v = { f2tf(pb[i].x), f2tf(pb[i].y), f2tf(pb[i].z), f2tf(pb[i].w) };
            *(uint4*)(bb + k * BSTR + n) = v;
        }
    };

    ldg_stage(0);
    sts_stage(0);
    __syncthreads();

    for (int s = 0; s < NST; s++) {
        int cb = s & 1;
        if (s + 1 < NST) ldg_stage((s + 1) * BK);
#pragma unroll
        for (int kk = 0; kk < 2; kk++) {
            uint32_t af[4][4];
#pragma unroll
            for (int i = 0; i < 4; i++)
                ldm4(af[i], a_base + (uint32_t)(cb * (ABUF * 4) + i * (16 * ASTR * 4) + kk * 32));
            const uint32_t* brow = (const uint32_t*)Bs + cb * BBUF
                                 + (kk * 8 + (lane & 3)) * BSTR + (lane >> 2);
#pragma unroll
            for (int j = 0; j < 8; j++) {
                uint32_t b0 = brow[nmap[j]];
                uint32_t b1 = brow[nmap[j] + 4 * BSTR];
#pragma unroll
                for (int i = 0; i < 4; i++) mma8(c[i][j], af[i], b0, b1);
            }
        }
        if (s + 1 < NST) sts_stage((s + 1) & 1);
        __syncthreads();
    }

    // epilogue: gu = gelu(gate) * up -> scratch (padded segment rows OK)
    int seg = g_segbase[e] + m0;
#pragma unroll
    for (int i = 0; i < 4; i++) {
        int r0 = wm * 64 + i * 16 + (lane >> 2);
#pragma unroll
        for (int j = 0; j < 4; j++) {
            int nc = n0 + wn * 32 + j * 8 + (lane & 3) * 2;
            float* gu = c[i][j]; float* uu = c[i][j + 4];
            float2 v0 = make_float2(gelu_tanh(gu[0]) * uu[0], gelu_tanh(gu[1]) * uu[1]);
            float2 v1 = make_float2(gelu_tanh(gu[2]) * uu[2], gelu_tanh(gu[3]) * uu[3]);
            *(float2*)(g_gu + (size_t)(seg + r0) * Id + nc)     = v0;
            *(float2*)(g_gu + (size_t)(seg + r0 + 8) * Id + nc) = v1;
        }
    }
}

// ---------------------------------------------------------------------------
// Down GEMM (mma.sync tf32): C[128x256] per CTA, scatter with atomics.
// ---------------------------------------------------------------------------
__global__ __launch_bounds__(THREADS, 1)
void down_mma(const float* __restrict__ dw, float* __restrict__ out) {
    int e  = blockIdx.z;
    int ne = g_count[e];
    int m0 = blockIdx.x * BM;
    if (m0 >= ne) return;
    int n0 = blockIdx.y * 256;

    extern __shared__ float smem[];
    float* As = smem;
    float* Bs = smem + 2 * ABUF;

    int tid = threadIdx.x;
    int lane = tid & 31, wid = tid >> 5;
    int wm = wid >> 2, wn = wid & 3;

    const float* abase = g_gu + (size_t)(g_segbase[e] + m0) * Id;
    const float* bbase = dw + (size_t)e * Id * Hd + n0;

    uint32_t a_base = (uint32_t)__cvta_generic_to_shared(As)
                    + (uint32_t)((wm * 64 + (lane & 15)) * (ASTR * 4) + (lane >> 4) * 16);

    float c[4][8][4];
#pragma unroll
    for (int i = 0; i < 4; i++)
#pragma unroll
        for (int j = 0; j < 8; j++)
#pragma unroll
            for (int q = 0; q < 4; q++) c[i][j][q] = 0.0f;

    float4 pa[2], pb[4];
    const int NST = Id / BK;

    auto ldg_stage = [&](int k0) {
#pragma unroll
        for (int i = 0; i < 2; i++) {
            int idx = tid + i * 256; int m = idx >> 2, ck = idx & 3;
            pa[i] = *(const float4*)(abase + (size_t)m * Id + k0 + ck * 4);
        }
#pragma unroll
        for (int i = 0; i < 4; i++) {
            int idx = tid + i * 256; int k = idx >> 6, n = (idx & 63) * 4;
            pb[i] = *(const float4*)(bbase + (size_t)(k0 + k) * Hd + n);
        }
    };
    auto sts_stage = [&](int b) {
        float* a  = As + b * ABUF;
        float* bb = Bs + b * BBUF;
#pragma unroll
        for (int i = 0; i < 2; i++) {
            int idx = tid + i * 256; int m = idx >> 2, ck = idx & 3;
            uint4 v = { f2tf(pa[i].x), f2tf(pa[i].y), f2tf(pa[i].z), f2tf(pa[i].w) };
            *(uint4*)(a + m * ASTR + ck * 4) = v;
        }
#pragma unroll
        for (int i = 0; i < 4; i++) {
            int idx = tid + i * 256; int k = idx >> 6, n = (idx & 63) * 4;
            uint4 v = { f2tf(pb[i].x), f2tf(pb[i].y), f2tf(pb[i].z), f2tf(pb[i].w) };
            *(uint4*)(bb + k * BSTR + n) = v;
        }
    };

    ldg_stage(0);
    sts_stage(0);
    __syncthreads();

    for (int s = 0; s < NST; s++) {
        int cb = s & 1;
        if (s + 1 < NST) ldg_stage((s + 1) * BK);
#pragma unroll
        for (int kk = 0; kk < 2; kk++) {
            uint32_t af[4][4];
#pragma unroll
            for (int i = 0; i < 4; i++)
                ldm4(af[i], a_base + (uint32_t)(cb * (ABUF * 4) + i * (16 * ASTR * 4) + kk * 32));
            const uint32_t* brow = (const uint32_t*)Bs + cb * BBUF
                                 + (kk * 8 + (lane & 3)) * BSTR + (lane >> 2);
#pragma unroll
            for (int j = 0; j < 8; j++) {
                uint32_t b0 = brow[wn * 64 + j * 8];
                uint32_t b1 = brow[wn * 64 + j * 8 + 4 * BSTR];
#pragma unroll
                for (int i = 0; i < 4; i++) mma8(c[i][j], af[i], b0, b1);
            }
        }
        if (s + 1 < NST) sts_stage((s + 1) & 1);
        __syncthreads();
    }

    // weighted scatter epilogue
#pragma unroll
    for (int i = 0; i < 4; i++) {
        int rl0 = m0 + wm * 64 + i * 16 + (lane >> 2);
        int rl1 = rl0 + 8;
        int   t0 = (rl0 < ne) ? g_tok[e][rl0] : -1;
        int   t1 = (rl1 < ne) ? g_tok[e][rl1] : -1;
        float w0 = (rl0 < ne) ? g_wt[e][rl0] : 0.0f;
        float w1 = (rl1 < ne) ? g_wt[e][rl1] : 0.0f;
#pragma unroll
        for (int j = 0; j < 8; j++) {
            int nc = n0 + wn * 64 + j * 8 + (lane & 3) * 2;
            if (t0 >= 0) {
                atomicAdd(out + (size_t)t0 * Hd + nc,     w0 * c[i][j][0]);
                atomicAdd(out + (size_t)t0 * Hd + nc + 1, w0 * c[i][j][1]);
            }
            if (t1 >= 0) {
                atomicAdd(out + (size_t)t1 * Hd + nc,     w1 * c[i][j][2]);
                atomicAdd(out + (size_t)t1 * Hd + nc + 1, w1 * c[i][j][3]);
            }
        }
    }
}

// ---------------------------------------------------------------------------
extern "C" void kernel_launch(void* const* d_in, const int* in_sizes, int n_in,
                              void* d_out, int out_size) {
    const float* x         = (const float*)d_in[0];
    const float* gate_w    = (const float*)d_in[1];
    const float* gate_proj = (const float*)d_in[2];
    const float* up_proj   = (const float*)d_in[3];
    const float* down_proj = (const float*)d_in[4];
    float* out = (float*)d_out;

    float* out_final  = out;
    float* out_logits = out + (size_t)T * Hd;

    static int attr_done = 0;
    cudaFuncSetAttribute(gateup_mma, cudaFuncAttributeMaxDynamicSharedMemorySize, DYN_SMEM);
    cudaFuncSetAttribute(down_mma,   cudaFuncAttributeMaxDynamicSharedMemorySize, DYN_SMEM);
    (void)attr_done;

    cudaMemsetAsync(out_final, 0, (size_t)T * Hd * sizeof(float));
    zero_counts_kernel<<<1, 32>>>();
    router_kernel<<<T / 8, 256>>>(x, gate_w, out_logits);
    prefix_kernel<<<1, 1>>>();

    dim3 g1(T / BM, Id / 128, NE);    // m fastest: weight L2 reuse across m-tiles
    gateup_mma<<<g1, THREADS, DYN_SMEM>>>(x, gate_proj, up_proj);

    dim3 g2(T / BM, Hd / 256, NE);
    down_mma<<<g2, THREADS, DYN_SMEM>>>(down_proj, out_final);
}

// round 6
// speedup vs baseline: 5.2450x; 1.9446x over previous
#include <cuda_runtime.h>
#include <cuda_fp16.h>
#include <math.h>
#include <stdint.h>

// Problem constants
#define Hd 2048
#define Id 4096
#define NE 8
#define T  4096

// GEMM tiling: CTA = 128m x 256n, BK=32 (fp16), 256 threads / 8 warps
#define BM 128
#define BK 32
#define THREADS 256
#define ASTR 40                       // halves per A row (32 + 8 pad) -> 80 B
#define ABYTES (BM * ASTR * 2)        // 10240
#define BSTR 264                      // halves per B k-row (256 + 8 pad) -> 528 B
#define BBYTES (BK * BSTR * 2)        // 16896
#define STAGE_BYTES (ABYTES + BBYTES) // 27136
#define NSTAGES 4
#define DYN_SMEM (NSTAGES * STAGE_BYTES)

// ---------------------------------------------------------------------------
// Static device scratch
// ---------------------------------------------------------------------------
#define GU_ROWS 9216
__device__ int    g_count[NE];
__device__ int    g_segbase[NE];
__device__ int    g_tok[NE][T];
__device__ float  g_wt[NE][T];
__device__ __align__(256) __half g_xh[(size_t)T * Hd];
__device__ __align__(256) __half g_gph[(size_t)NE * Hd * Id];
__device__ __align__(256) __half g_uph[(size_t)NE * Hd * Id];
__device__ __align__(256) __half g_dwh[(size_t)NE * Id * Hd];
__device__ __align__(256) __half g_guh[(size_t)GU_ROWS * Id];

// ---------------------------------------------------------------------------
// PTX helpers (compute_103-legal)
// ---------------------------------------------------------------------------
__device__ __forceinline__ void cp16(uint32_t dst, const void* src) {
    asm volatile("cp.async.cg.shared.global [%0], [%1], 16;" :: "r"(dst), "l"(src));
}
__device__ __forceinline__ void ldm4(uint32_t* r, uint32_t addr) {
    asm volatile("ldmatrix.sync.aligned.m8n8.x4.shared.b16 {%0,%1,%2,%3}, [%4];"
                 : "=r"(r[0]), "=r"(r[1]), "=r"(r[2]), "=r"(r[3]) : "r"(addr));
}
__device__ __forceinline__ void ldm4t(uint32_t* r, uint32_t addr) {
    asm volatile("ldmatrix.sync.aligned.m8n8.x4.trans.shared.b16 {%0,%1,%2,%3}, [%4];"
                 : "=r"(r[0]), "=r"(r[1]), "=r"(r[2]), "=r"(r[3]) : "r"(addr));
}
__device__ __forceinline__ void mma16(float* c, const uint32_t* a, uint32_t b0, uint32_t b1) {
    asm volatile("mma.sync.aligned.m16n8k16.row.col.f32.f16.f16.f32 "
        "{%0,%1,%2,%3}, {%4,%5,%6,%7}, {%8,%9}, {%0,%1,%2,%3};"
        : "+f"(c[0]), "+f"(c[1]), "+f"(c[2]), "+f"(c[3])
        : "r"(a[0]), "r"(a[1]), "r"(a[2]), "r"(a[3]), "r"(b0), "r"(b1));
}
__device__ __forceinline__ float gelu_tanh(float v) {
    const float c = 0.7978845608028654f;
    float inner = c * (v + 0.044715f * v * v * v);
    return 0.5f * v * (1.0f + tanhf(inner));
}

// ---------------------------------------------------------------------------
// fp32 -> fp16 conversion (grid-stride, float4)
// ---------------------------------------------------------------------------
__global__ void cvt_kernel(const float* __restrict__ s, __half* __restrict__ d, int n4) {
    int i = blockIdx.x * blockDim.x + threadIdx.x;
    int stride = gridDim.x * blockDim.x;
    for (; i < n4; i += stride) {
        float4 v = ((const float4*)s)[i];
        __half2 h0 = __floats2half2_rn(v.x, v.y);
        __half2 h1 = __floats2half2_rn(v.z, v.w);
        ((__half2*)d)[2 * i]     = h0;
        ((__half2*)d)[2 * i + 1] = h1;
    }
}

// ---------------------------------------------------------------------------
// Router + bookkeeping
// ---------------------------------------------------------------------------
__global__ void zero_counts_kernel() {
    if (threadIdx.x < NE) g_count[threadIdx.x] = 0;
}
__global__ void prefix_kernel() {
    if (threadIdx.x == 0) {
        int b = 0;
        for (int e = 0; e < NE; e++) {
            g_segbase[e] = b;
            b += ((g_count[e] + BM - 1) / BM) * BM;
        }
    }
}

__global__ void router_kernel(const float* __restrict__ x,
                              const float* __restrict__ gw,
                              float* __restrict__ out_logits) {
    int warp = (blockIdx.x * blockDim.x + threadIdx.x) >> 5;
    int lane = threadIdx.x & 31;
    if (warp >= T) return;
    const float* xr = x + (size_t)warp * Hd;
    float acc[NE];
#pragma unroll
    for (int e = 0; e < NE; e++) acc[e] = 0.0f;
    for (int h = lane; h < Hd; h += 32) {
        float xv = xr[h];
        const float* g = gw + (size_t)h * NE;
#pragma unroll
        for (int e = 0; e < NE; e++) acc[e] = fmaf(xv, g[e], acc[e]);
    }
#pragma unroll
    for (int e = 0; e < NE; e++) {
#pragma unroll
        for (int off = 16; off; off >>= 1)
            acc[e] += __shfl_xor_sync(0xffffffffu, acc[e], off);
    }
    if (lane == 0) {
        float* dst = out_logits + (size_t)warp * NE;
#pragma unroll
        for (int e = 0; e < NE; e++) dst[e] = acc[e];
        float l0 = -3.4e38f; int e0 = 0;
#pragma unroll
        for (int e = 0; e < NE; e++)
            if (acc[e] > l0) { l0 = acc[e]; e0 = e; }
        float l1 = -3.4e38f; int e1 = 0;
#pragma unroll
        for (int e = 0; e < NE; e++)
            if (e != e0 && acc[e] > l1) { l1 = acc[e]; e1 = e; }
        float w1 = __expf(l1 - l0);
        float inv = 1.0f / (1.0f + w1);
        int p0 = atomicAdd(&g_count[e0], 1);
        g_tok[e0][p0] = warp; g_wt[e0][p0] = inv;
        int p1 = atomicAdd(&g_count[e1], 1);
        g_tok[e1][p1] = warp; g_wt[e1][p1] = w1 * inv;
    }
}

// ---------------------------------------------------------------------------
// Gate+Up GEMM (fp16 mma.sync): per CTA 128m x (128 gate + 128 up), K=Hd.
// ---------------------------------------------------------------------------
__global__ __launch_bounds__(THREADS, 1)
void gateup_mma(void) {
    int e  = blockIdx.z;
    int ne = g_count[e];
    int m0 = blockIdx.x * BM;
    if (m0 >= ne) return;
    int n0 = blockIdx.y * 128;

    extern __shared__ char smem[];
    uint32_t sbase = (uint32_t)__cvta_generic_to_shared(smem);
    __shared__ int rows[BM];

    int tid = threadIdx.x;
    int lane = tid & 31, wid = tid >> 5;
    int wm = wid >> 2, wn = wid & 3;

    if (tid < BM) {
        int m = m0 + tid;
        rows[tid] = g_tok[e][m < ne ? m : (ne - 1)];
    }
    __syncthreads();

    const __half* gbh = g_gph + (size_t)e * Hd * Id + n0;
    const __half* ubh = g_uph + (size_t)e * Hd * Id + n0;

    // ldmatrix lane bases
    uint32_t a_lane = sbase + (uint32_t)((wm * 64 + (lane & 15)) * (ASTR * 2) + (lane >> 4) * 16);
    uint32_t b_lane = sbase + (uint32_t)ABYTES
                    + (uint32_t)((((lane & 7) + ((lane >> 3) & 1) * 8) * (BSTR * 2)) + (lane >> 4) * 16);
    int nmap2[4] = { wn * 32, wn * 32 + 16, 128 + wn * 32, 128 + wn * 32 + 16 };

    float c[4][8][4];
#pragma unroll
    for (int i = 0; i < 4; i++)
#pragma unroll
        for (int j = 0; j < 8; j++)
#pragma unroll
            for (int q = 0; q < 4; q++) c[i][j][q] = 0.0f;

    const int NST = Hd / BK;   // 64

    auto issue = [&](int s) {
        int k0 = s * BK;
        uint32_t a_s = sbase + (uint32_t)((s & 3) * STAGE_BYTES);
        uint32_t b_s = a_s + ABYTES;
#pragma unroll
        for (int i = 0; i < 2; i++) {
            int cidx = tid + i * 256;
            int m = cidx >> 2, ch = cidx & 3;
            cp16(a_s + m * (ASTR * 2) + ch * 16,
                 g_xh + (size_t)rows[m] * Hd + k0 + ch * 8);
        }
#pragma unroll
        for (int i = 0; i < 4; i++) {
            int cidx = tid + i * 256;
            int k = cidx >> 5, nn = (cidx & 31) * 8;
            const __half* src = (nn < 128) ? (gbh + (size_t)(k0 + k) * Id + nn)
                                           : (ubh + (size_t)(k0 + k) * Id + (nn - 128));
            cp16(b_s + k * (BSTR * 2) + nn * 2, src);
        }
        asm volatile("cp.async.commit_group;" ::: "memory");
    };

    issue(0); issue(1); issue(2);

    for (int s = 0; s < NST; s++) {
        asm volatile("cp.async.wait_group 2;" ::: "memory");
        __syncthreads();
        if (s + 3 < NST) issue(s + 3);

        uint32_t stg = (uint32_t)((s & 3) * STAGE_BYTES);
#pragma unroll
        for (int kk = 0; kk < 2; kk++) {
            uint32_t af[4][4], bf[4][4];
#pragma unroll
            for (int i = 0; i < 4; i++)
                ldm4(af[i], a_lane + stg + (uint32_t)(i * 16 * ASTR * 2 + kk * 32));
#pragma unroll
            for (int j2 = 0; j2 < 4; j2++)
                ldm4t(bf[j2], b_lane + stg + (uint32_t)(kk * 16 * BSTR * 2 + nmap2[j2] * 2));
#pragma unroll
            for (int j = 0; j < 8; j++) {
                uint32_t b0 = bf[j >> 1][(j & 1) * 2];
                uint32_t b1 = bf[j >> 1][(j & 1) * 2 + 1];
#pragma unroll
                for (int i = 0; i < 4; i++) mma16(c[i][j], af[i], b0, b1);
            }
        }
    }

    // epilogue: gu = gelu(gate) * up -> fp16 scratch
    int seg = g_segbase[e] + m0;
#pragma unroll
    for (int i = 0; i < 4; i++) {
        int r0 = wm * 64 + i * 16 + (lane >> 2);
#pragma unroll
        for (int j = 0; j < 4; j++) {
            int nc = n0 + wn * 32 + j * 8 + (lane & 3) * 2;
            float* gg = c[i][j]; float* uu = c[i][j + 4];
            __half2 v0 = __floats2half2_rn(gelu_tanh(gg[0]) * uu[0], gelu_tanh(gg[1]) * uu[1]);
            __half2 v1 = __floats2half2_rn(gelu_tanh(gg[2]) * uu[2], gelu_tanh(gg[3]) * uu[3]);
            *(__half2*)(g_guh + (size_t)(seg + r0) * Id + nc)     = v0;
            *(__half2*)(g_guh + (size_t)(seg + r0 + 8) * Id + nc) = v1;
        }
    }
}

// ---------------------------------------------------------------------------
// Down GEMM (fp16 mma.sync): per CTA 128m x 256n, K=Id, weighted atomic scatter.
// ---------------------------------------------------------------------------
__global__ __launch_bounds__(THREADS, 1)
void down_mma(float* __restrict__ out) {
    int e  = blockIdx.z;
    int ne = g_count[e];
    int m0 = blockIdx.x * BM;
    if (m0 >= ne) return;
    int n0 = blockIdx.y * 256;

    extern __shared__ char smem[];
    uint32_t sbase = (uint32_t)__cvta_generic_to_shared(smem);

    int tid = threadIdx.x;
    int lane = tid & 31, wid = tid >> 5;
    int wm = wid >> 2, wn = wid & 3;

    const __half* abase = g_guh + (size_t)(g_segbase[e] + m0) * Id;
    const __half* bbase = g_dwh + (size_t)e * Id * Hd + n0;

    uint32_t a_lane = sbase + (uint32_t)((wm * 64 + (lane & 15)) * (ASTR * 2) + (lane >> 4) * 16);
    uint32_t b_lane = sbase + (uint32_t)ABYTES
                    + (uint32_t)((((lane & 7) + ((lane >> 3) & 1) * 8) * (BSTR * 2)) + (lane >> 4) * 16);
    int nmap2[4] = { wn * 64, wn * 64 + 16, wn * 64 + 32, wn * 64 + 48 };

    float c[4][8][4];
#pragma unroll
    for (int i = 0; i < 4; i++)
#pragma unroll
        for (int j = 0; j < 8; j++)
#pragma unroll
            for (int q = 0; q < 4; q++) c[i][j][q] = 0.0f;

    const int NST = Id / BK;   // 128

    auto issue = [&](int s) {
        int k0 = s * BK;
        uint32_t a_s = sbase + (uint32_t)((s & 3) * STAGE_BYTES);
        uint32_t b_s = a_s + ABYTES;
#pragma unroll
        for (int i = 0; i < 2; i++) {
            int cidx = tid + i * 256;
            int m = cidx >> 2, ch = cidx & 3;
            cp16(a_s + m * (ASTR * 2) + ch * 16,
                 abase + (size_t)m * Id + k0 + ch * 8);
        }
#pragma unroll
        for (int i = 0; i < 4; i++) {
            int cidx = tid + i * 256;
            int k = cidx >> 5, nn = (cidx & 31) * 8;
            cp16(b_s + k * (BSTR * 2) + nn * 2,
                 bbase + (size_t)(k0 + k) * Hd + nn);
        }
        asm volatile("cp.async.commit_group;" ::: "memory");
    };

    issue(0); issue(1); issue(2);

    for (int s = 0; s < NST; s++) {
        asm volatile("cp.async.wait_group 2;" ::: "memory");
        __syncthreads();
        if (s + 3 < NST) issue(s + 3);

        uint32_t stg = (uint32_t)((s & 3) * STAGE_BYTES);
#pragma unroll
        for (int kk = 0; kk < 2; kk++) {
            uint32_t af[4][4], bf[4][4];
#pragma unroll
            for (int i = 0; i < 4; i++)
                ldm4(af[i], a_lane + stg + (uint32_t)(i * 16 * ASTR * 2 + kk * 32));
#pragma unroll
            for (int j2 = 0; j2 < 4; j2++)
                ldm4t(bf[j2], b_lane + stg + (uint32_t)(kk * 16 * BSTR * 2 + nmap2[j2] * 2));
#pragma unroll
            for (int j = 0; j < 8; j++) {
                uint32_t b0 = bf[j >> 1][(j & 1) * 2];
                uint32_t b1 = bf[j >> 1][(j & 1) * 2 + 1];
#pragma unroll
                for (int i = 0; i < 4; i++) mma16(c[i][j], af[i], b0, b1);
            }
        }
    }

    // weighted scatter epilogue
#pragma unroll
    for (int i = 0; i < 4; i++) {
        int rl0 = m0 + wm * 64 + i * 16 + (lane >> 2);
        int rl1 = rl0 + 8;
        int   t0 = (rl0 < ne) ? g_tok[e][rl0] : -1;
        int   t1 = (rl1 < ne) ? g_tok[e][rl1] : -1;
        float w0 = (rl0 < ne) ? g_wt[e][rl0] : 0.0f;
        float w1 = (rl1 < ne) ? g_wt[e][rl1] : 0.0f;
#pragma unroll
        for (int j = 0; j < 8; j++) {
            int nc = n0 + wn * 64 + j * 8 + (lane & 3) * 2;
            if (t0 >= 0) {
                atomicAdd(out + (size_t)t0 * Hd + nc,     w0 * c[i][j][0]);
                atomicAdd(out + (size_t)t0 * Hd + nc + 1, w0 * c[i][j][1]);
            }
            if (t1 >= 0) {
                atomicAdd(out + (size_t)t1 * Hd + nc,     w1 * c[i][j][2]);
                atomicAdd(out + (size_t)t1 * Hd + nc + 1, w1 * c[i][j][3]);
            }
        }
    }
}

// ---------------------------------------------------------------------------
extern "C" void kernel_launch(void* const* d_in, const int* in_sizes, int n_in,
                              void* d_out, int out_size) {
    const float* x         = (const float*)d_in[0];
    const float* gate_w    = (const float*)d_in[1];
    const float* gate_proj = (const float*)d_in[2];
    const float* up_proj   = (const float*)d_in[3];
    const float* down_proj = (const float*)d_in[4];
    float* out = (float*)d_out;

    float* out_final  = out;
    float* out_logits = out + (size_t)T * Hd;

    cudaFuncSetAttribute(gateup_mma, cudaFuncAttributeMaxDynamicSharedMemorySize, DYN_SMEM);
    cudaFuncSetAttribute(down_mma,   cudaFuncAttributeMaxDynamicSharedMemorySize, DYN_SMEM);

    cudaMemsetAsync(out_final, 0, (size_t)T * Hd * sizeof(float));
    zero_counts_kernel<<<1, 32>>>();

    // fp32 -> fp16 conversions (resolve device-symbol addresses via a static once;
    // cudaGetSymbolAddress is host-side and capture-safe)
    static __half *xh = nullptr, *gph = nullptr, *uph = nullptr, *dwh = nullptr;
    if (!xh) {
        cudaGetSymbolAddress((void**)&xh,  g_xh);
        cudaGetSymbolAddress((void**)&gph, g_gph);
        cudaGetSymbolAddress((void**)&uph, g_uph);
        cudaGetSymbolAddress((void**)&dwh, g_dwh);
    }
    const int WN4 = (NE * Hd * Id) / 4;   // 16M float4 per weight tensor
    cvt_kernel<<<4096, 256>>>(x,         xh,  (T * Hd) / 4);
    cvt_kernel<<<8192, 256>>>(gate_proj, gph, WN4);
    cvt_kernel<<<8192, 256>>>(up_proj,   uph, WN4);
    cvt_kernel<<<8192, 256>>>(down_proj, dwh, WN4);

    router_kernel<<<T / 8, 256>>>(x, gate_w, out_logits);
    prefix_kernel<<<1, 1>>>();

    dim3 g1(T / BM, Id / 128, NE);   // m fastest: B-slice L2 reuse across m-tiles
    gateup_mma<<<g1, THREADS, DYN_SMEM>>>();

    dim3 g2(T / BM, Hd / 256, NE);
    down_mma<<<g2, THREADS, DYN_SMEM>>>(out_final);
}

// round 8
// speedup vs baseline: 5.5001x; 1.0486x over previous
#include <cuda_runtime.h>
#include <cuda_fp16.h>
#include <math.h>
#include <stdint.h>

// Problem constants
#define Hd 2048
#define Id 4096
#define NE 8
#define T  4096

// GEMM tiling: CTA = 128m x 256n, BK=64 (fp16), 256 threads / 8 warps
#define BM 128
#define BK 64
#define THREADS 256
#define ASTR 72                       // halves per A row (64 + 8 pad) -> 144 B
#define ABYTES (BM * ASTR * 2)        // 18432
#define BSTR 264                      // halves per B k-row (256 + 8 pad) -> 528 B
#define BBYTES (BK * BSTR * 2)        // 33792
#define STAGE_BYTES (ABYTES + BBYTES) // 52224
#define NSTAGES 4
#define DYN_SMEM (NSTAGES * STAGE_BYTES)   // 208896

// ---------------------------------------------------------------------------
// Static device scratch
// ---------------------------------------------------------------------------
#define GU_ROWS 9216
__device__ int    g_count[NE];
__device__ int    g_segbase[NE];
__device__ int    g_tok[NE][T];
__device__ float  g_wt[NE][T];
__device__ __align__(256) __half g_xh[(size_t)T * Hd];
__device__ __align__(256) __half g_gph[(size_t)NE * Hd * Id];
__device__ __align__(256) __half g_uph[(size_t)NE * Hd * Id];
__device__ __align__(256) __half g_dwh[(size_t)NE * Id * Hd];
__device__ __align__(256) __half g_guh[(size_t)GU_ROWS * Id];

// ---------------------------------------------------------------------------
// PTX helpers (compute_103-legal)
// ---------------------------------------------------------------------------
__device__ __forceinline__ void cp16(uint32_t dst, const void* src) {
    asm volatile("cp.async.cg.shared.global [%0], [%1], 16;" :: "r"(dst), "l"(src));
}
__device__ __forceinline__ void ldm4(uint32_t* r, uint32_t addr) {
    asm volatile("ldmatrix.sync.aligned.m8n8.x4.shared.b16 {%0,%1,%2,%3}, [%4];"
                 : "=r"(r[0]), "=r"(r[1]), "=r"(r[2]), "=r"(r[3]) : "r"(addr));
}
__device__ __forceinline__ void ldm4t(uint32_t* r, uint32_t addr) {
    asm volatile("ldmatrix.sync.aligned.m8n8.x4.trans.shared.b16 {%0,%1,%2,%3}, [%4];"
                 : "=r"(r[0]), "=r"(r[1]), "=r"(r[2]), "=r"(r[3]) : "r"(addr));
}
__device__ __forceinline__ void mma16(float* c, const uint32_t* a, uint32_t b0, uint32_t b1) {
    asm volatile("mma.sync.aligned.m16n8k16.row.col.f32.f16.f16.f32 "
        "{%0,%1,%2,%3}, {%4,%5,%6,%7}, {%8,%9}, {%0,%1,%2,%3};"
        : "+f"(c[0]), "+f"(c[1]), "+f"(c[2]), "+f"(c[3])
        : "r"(a[0]), "r"(a[1]), "r"(a[2]), "r"(a[3]), "r"(b0), "r"(b1));
}
__device__ __forceinline__ float gelu_tanh(float v) {
    const float c = 0.7978845608028654f;
    float inner = c * (v + 0.044715f * v * v * v);
    return 0.5f * v * (1.0f + tanhf(inner));
}
// Tail-correct pipeline wait: guarantee stage s is resident.
#define PIPE_WAIT(s, nst)                                                  \
    do {                                                                   \
        if ((s) + 1 >= (nst))      asm volatile("cp.async.wait_group 0;" ::: "memory"); \
        else if ((s) + 2 >= (nst)) asm volatile("cp.async.wait_group 1;" ::: "memory"); \
        else                       asm volatile("cp.async.wait_group 2;" ::: "memory"); \
    } while (0)

// ---------------------------------------------------------------------------
// fp32 -> fp16 conversion (grid-stride, float4)
// ---------------------------------------------------------------------------
__global__ void cvt_kernel(const float* __restrict__ s, __half* __restrict__ d, int n4) {
    int i = blockIdx.x * blockDim.x + threadIdx.x;
    int stride = gridDim.x * blockDim.x;
    for (; i < n4; i += stride) {
        float4 v = ((const float4*)s)[i];
        __half2 h0 = __floats2half2_rn(v.x, v.y);
        __half2 h1 = __floats2half2_rn(v.z, v.w);
        ((__half2*)d)[2 * i]     = h0;
        ((__half2*)d)[2 * i + 1] = h1;
    }
}

// ---------------------------------------------------------------------------
// Router + bookkeeping
// ---------------------------------------------------------------------------
__global__ void zero_counts_kernel() {
    if (threadIdx.x < NE) g_count[threadIdx.x] = 0;
}
__global__ void prefix_kernel() {
    if (threadIdx.x == 0) {
        int b = 0;
        for (int e = 0; e < NE; e++) {
            g_segbase[e] = b;
            b += ((g_count[e] + BM - 1) / BM) * BM;
        }
    }
}

__global__ void router_kernel(const float* __restrict__ x,
                              const float* __restrict__ gw,
                              float* __restrict__ out_logits) {
    int warp = (blockIdx.x * blockDim.x + threadIdx.x) >> 5;
    int lane = threadIdx.x & 31;
    if (warp >= T) return;
    const float* xr = x + (size_t)warp * Hd;
    float acc[NE];
#pragma unroll
    for (int e = 0; e < NE; e++) acc[e] = 0.0f;
    for (int h = lane; h < Hd; h += 32) {
        float xv = xr[h];
        const float* g = gw + (size_t)h * NE;
#pragma unroll
        for (int e = 0; e < NE; e++) acc[e] = fmaf(xv, g[e], acc[e]);
    }
#pragma unroll
    for (int e = 0; e < NE; e++) {
#pragma unroll
        for (int off = 16; off; off >>= 1)
            acc[e] += __shfl_xor_sync(0xffffffffu, acc[e], off);
    }
    if (lane == 0) {
        float* dst = out_logits + (size_t)warp * NE;
#pragma unroll
        for (int e = 0; e < NE; e++) dst[e] = acc[e];
        float l0 = -3.4e38f; int e0 = 0;
#pragma unroll
        for (int e = 0; e < NE; e++)
            if (acc[e] > l0) { l0 = acc[e]; e0 = e; }
        float l1 = -3.4e38f; int e1 = 0;
#pragma unroll
        for (int e = 0; e < NE; e++)
            if (e != e0 && acc[e] > l1) { l1 = acc[e]; e1 = e; }
        float w1 = __expf(l1 - l0);
        float inv = 1.0f / (1.0f + w1);
        int p0 = atomicAdd(&g_count[e0], 1);
        g_tok[e0][p0] = warp; g_wt[e0][p0] = inv;
        int p1 = atomicAdd(&g_count[e1], 1);
        g_tok[e1][p1] = warp; g_wt[e1][p1] = w1 * inv;
    }
}

// ---------------------------------------------------------------------------
// Gate+Up GEMM (fp16 mma.sync): per CTA 128m x (128 gate + 128 up), K=Hd.
// ---------------------------------------------------------------------------
__global__ __launch_bounds__(THREADS, 1)
void gateup_mma(void) {
    int e  = blockIdx.z;
    int ne = g_count[e];
    int m0 = blockIdx.x * BM;
    if (m0 >= ne) return;
    int n0 = blockIdx.y * 128;

    extern __shared__ char smem[];
    uint32_t sbase = (uint32_t)__cvta_generic_to_shared(smem);
    __shared__ int rows[BM];

    int tid = threadIdx.x;
    int lane = tid & 31, wid = tid >> 5;
    int wm = wid >> 2, wn = wid & 3;

    if (tid < BM) {
        int m = m0 + tid;
        rows[tid] = g_tok[e][m < ne ? m : (ne - 1)];
    }
    __syncthreads();

    const __half* gbh = g_gph + (size_t)e * Hd * Id + n0;
    const __half* ubh = g_uph + (size_t)e * Hd * Id + n0;

    uint32_t a_lane = sbase + (uint32_t)((wm * 64 + (lane & 15)) * (ASTR * 2) + (lane >> 4) * 16);
    uint32_t b_lane = sbase + (uint32_t)ABYTES
                    + (uint32_t)((((lane & 7) + ((lane >> 3) & 1) * 8) * (BSTR * 2)) + (lane >> 4) * 16);
    int nmap2[4] = { wn * 32, wn * 32 + 16, 128 + wn * 32, 128 + wn * 32 + 16 };

    float c[4][8][4];
#pragma unroll
    for (int i = 0; i < 4; i++)
#pragma unroll
        for (int j = 0; j < 8; j++)
#pragma unroll
            for (int q = 0; q < 4; q++) c[i][j][q] = 0.0f;

    const int NST = Hd / BK;   // 32

    auto issue = [&](int s) {
        int k0 = s * BK;
        uint32_t a_s = sbase + (uint32_t)((s & 3) * STAGE_BYTES);
        uint32_t b_s = a_s + ABYTES;
#pragma unroll
        for (int i = 0; i < 4; i++) {              // 1024 A chunks
            int cidx = tid + i * 256;
            int m = cidx >> 3, ch = cidx & 7;
            cp16(a_s + m * (ASTR * 2) + ch * 16,
                 g_xh + (size_t)rows[m] * Hd + k0 + ch * 8);
        }
#pragma unroll
        for (int i = 0; i < 8; i++) {              // 2048 B chunks
            int cidx = tid + i * 256;
            int k = cidx >> 5, nn = (cidx & 31) * 8;
            const __half* src = (nn < 128) ? (gbh + (size_t)(k0 + k) * Id + nn)
                                           : (ubh + (size_t)(k0 + k) * Id + (nn - 128));
            cp16(b_s + k * (BSTR * 2) + nn * 2, src);
        }
        asm volatile("cp.async.commit_group;" ::: "memory");
    };

    issue(0); issue(1); issue(2);

    for (int s = 0; s < NST; s++) {
        PIPE_WAIT(s, NST);
        __syncthreads();
        if (s + 3 < NST) issue(s + 3);   // buffer (s+3)&3 == (s-1)&3: consumed, barrier-safe

        uint32_t stg = (uint32_t)((s & 3) * STAGE_BYTES);
#pragma unroll
        for (int kk = 0; kk < 4; kk++) {
            uint32_t af[4][4], bf[4][4];
#pragma unroll
            for (int i = 0; i < 4; i++)
                ldm4(af[i], a_lane + stg + (uint32_t)(i * 16 * ASTR * 2 + kk * 32));
#pragma unroll
            for (int j2 = 0; j2 < 4; j2++)
                ldm4t(bf[j2], b_lane + stg + (uint32_t)(kk * 16 * BSTR * 2 + nmap2[j2] * 2));
#pragma unroll
            for (int j = 0; j < 8; j++) {
                uint32_t b0 = bf[j >> 1][(j & 1) * 2];
                uint32_t b1 = bf[j >> 1][(j & 1) * 2 + 1];
#pragma unroll
                for (int i = 0; i < 4; i++) mma16(c[i][j], af[i], b0, b1);
            }
        }
    }

    // epilogue: gu = gelu(gate) * up -> fp16 scratch
    int seg = g_segbase[e] + m0;
#pragma unroll
    for (int i = 0; i < 4; i++) {
        int r0 = wm * 64 + i * 16 + (lane >> 2);
#pragma unroll
        for (int j = 0; j < 4; j++) {
            int nc = n0 + wn * 32 + j * 8 + (lane & 3) * 2;
            float* gg = c[i][j]; float* uu = c[i][j + 4];
            __half2 v0 = __floats2half2_rn(gelu_tanh(gg[0]) * uu[0], gelu_tanh(gg[1]) * uu[1]);
            __half2 v1 = __floats2half2_rn(gelu_tanh(gg[2]) * uu[2], gelu_tanh(gg[3]) * uu[3]);
            *(__half2*)(g_guh + (size_t)(seg + r0) * Id + nc)     = v0;
            *(__half2*)(g_guh + (size_t)(seg + r0 + 8) * Id + nc) = v1;
        }
    }
}

// ---------------------------------------------------------------------------
// Down GEMM (fp16 mma.sync): per CTA 128m x 256n, K=Id, weighted atomic scatter.
// ---------------------------------------------------------------------------
__global__ __launch_bounds__(THREADS, 1)
void down_mma(float* __restrict__ out) {
    int e  = blockIdx.z;
    int ne = g_count[e];
    int m0 = blockIdx.x * BM;
    if (m0 >= ne) return;
    int n0 = blockIdx.y * 256;

    extern __shared__ char smem[];
    uint32_t sbase = (uint32_t)__cvta_generic_to_shared(smem);

    int tid = threadIdx.x;
    int lane = tid & 31, wid = tid >> 5;
    int wm = wid >> 2, wn = wid & 3;

    const __half* abase = g_guh + (size_t)(g_segbase[e] + m0) * Id;
    const __half* bbase = g_dwh + (size_t)e * Id * Hd + n0;

    uint32_t a_lane = sbase + (uint32_t)((wm * 64 + (lane & 15)) * (ASTR * 2) + (lane >> 4) * 16);
    uint32_t b_lane = sbase + (uint32_t)ABYTES
                    + (uint32_t)((((lane & 7) + ((lane >> 3) & 1) * 8) * (BSTR * 2)) + (lane >> 4) * 16);
    int nmap2[4] = { wn * 64, wn * 64 + 16, wn * 64 + 32, wn * 64 + 48 };

    float c[4][8][4];
#pragma unroll
    for (int i = 0; i < 4; i++)
#pragma unroll
        for (int j = 0; j < 8; j++)
#pragma unroll
            for (int q = 0; q < 4; q++) c[i][j][q] = 0.0f;

    const int NST = Id / BK;   // 64

    auto issue = [&](int s) {
        int k0 = s * BK;
        uint32_t a_s = sbase + (uint32_t)((s & 3) * STAGE_BYTES);
        uint32_t b_s = a_s + ABYTES;
#pragma unroll
        for (int i = 0; i < 4; i++) {
            int cidx = tid + i * 256;
            int m = cidx >> 3, ch = cidx & 7;
            cp16(a_s + m * (ASTR * 2) + ch * 16,
                 abase + (size_t)m * Id + k0 + ch * 8);
        }
#pragma unroll
        for (int i = 0; i < 8; i++) {
            int cidx = tid + i * 256;
            int k = cidx >> 5, nn = (cidx & 31) * 8;
            cp16(b_s + k * (BSTR * 2) + nn * 2,
                 bbase + (size_t)(k0 + k) * Hd + nn);
        }
        asm volatile("cp.async.commit_group;" ::: "memory");
    };

    issue(0); issue(1); issue(2);

    for (int s = 0; s < NST; s++) {
        PIPE_WAIT(s, NST);
        __syncthreads();
        if (s + 3 < NST) issue(s + 3);

        uint32_t stg = (uint32_t)((s & 3) * STAGE_BYTES);
#pragma unroll
        for (int kk = 0; kk < 4; kk++) {
            uint32_t af[4][4], bf[4][4];
#pragma unroll
            for (int i = 0; i < 4; i++)
                ldm4(af[i], a_lane + stg + (uint32_t)(i * 16 * ASTR * 2 + kk * 32));
#pragma unroll
            for (int j2 = 0; j2 < 4; j2++)
                ldm4t(bf[j2], b_lane + stg + (uint32_t)(kk * 16 * BSTR * 2 + nmap2[j2] * 2));
#pragma unroll
            for (int j = 0; j < 8; j++) {
                uint32_t b0 = bf[j >> 1][(j & 1) * 2];
                uint32_t b1 = bf[j >> 1][(j & 1) * 2 + 1];
#pragma unroll
                for (int i = 0; i < 4; i++) mma16(c[i][j], af[i], b0, b1);
            }
        }
    }

    // weighted scatter epilogue
#pragma unroll
    for (int i = 0; i < 4; i++) {
        int rl0 = m0 + wm * 64 + i * 16 + (lane >> 2);
        int rl1 = rl0 + 8;
        int   t0 = (rl0 < ne) ? g_tok[e][rl0] : -1;
        int   t1 = (rl1 < ne) ? g_tok[e][rl1] : -1;
        float w0 = (rl0 < ne) ? g_wt[e][rl0] : 0.0f;
        float w1 = (rl1 < ne) ? g_wt[e][rl1] : 0.0f;
#pragma unroll
        for (int j = 0; j < 8; j++) {
            int nc = n0 + wn * 64 + j * 8 + (lane & 3) * 2;
            if (t0 >= 0) {
                atomicAdd(out + (size_t)t0 * Hd + nc,     w0 * c[i][j][0]);
                atomicAdd(out + (size_t)t0 * Hd + nc + 1, w0 * c[i][j][1]);
            }
            if (t1 >= 0) {
                atomicAdd(out + (size_t)t1 * Hd + nc,     w1 * c[i][j][2]);
                atomicAdd(out + (size_t)t1 * Hd + nc + 1, w1 * c[i][j][3]);
            }
        }
    }
}

// ---------------------------------------------------------------------------
extern "C" void kernel_launch(void* const* d_in, const int* in_sizes, int n_in,
                              void* d_out, int out_size) {
    const float* x         = (const float*)d_in[0];
    const float* gate_w    = (const float*)d_in[1];
    const float* gate_proj = (const float*)d_in[2];
    const float* up_proj   = (const float*)d_in[3];
    const float* down_proj = (const float*)d_in[4];
    float* out = (float*)d_out;

    float* out_final  = out;
    float* out_logits = out + (size_t)T * Hd;

    cudaFuncSetAttribute(gateup_mma, cudaFuncAttributeMaxDynamicSharedMemorySize, DYN_SMEM);
    cudaFuncSetAttribute(down_mma,   cudaFuncAttributeMaxDynamicSharedMemorySize, DYN_SMEM);

    cudaMemsetAsync(out_final, 0, (size_t)T * Hd * sizeof(float));
    zero_counts_kernel<<<1, 32>>>();

    static __half *xh = nullptr, *gph = nullptr, *uph = nullptr, *dwh = nullptr;
    if (!xh) {
        cudaGetSymbolAddress((void**)&xh,  g_xh);
        cudaGetSymbolAddress((void**)&gph, g_gph);
        cudaGetSymbolAddress((void**)&uph, g_uph);
        cudaGetSymbolAddress((void**)&dwh, g_dwh);
    }
    const int WN4 = (NE * Hd * Id) / 4;
    cvt_kernel<<<4096, 256>>>(x,         xh,  (T * Hd) / 4);
    cvt_kernel<<<8192, 256>>>(gate_proj, gph, WN4);
    cvt_kernel<<<8192, 256>>>(up_proj,   uph, WN4);
    cvt_kernel<<<8192, 256>>>(down_proj, dwh, WN4);

    router_kernel<<<T / 8, 256>>>(x, gate_w, out_logits);
    prefix_kernel<<<1, 1>>>();

    dim3 g1(T / BM, Id / 128, NE);   // m fastest: B-slice L2 reuse across m-tiles
    gateup_mma<<<g1, THREADS, DYN_SMEM>>>();

    dim3 g2(T / BM, Hd / 256, NE);
    down_mma<<<g2, THREADS, DYN_SMEM>>>(out_final);
}

// round 10
// speedup vs baseline: 5.5909x; 1.0165x over previous
#include <cuda_runtime.h>
#include <cuda_fp16.h>
#include <math.h>
#include <stdint.h>

// Problem constants
#define Hd 2048
#define Id 4096
#define NE 8
#define T  4096

// GEMM tiling: CTA = 128m x 256n, BK=64 (fp16), 512 threads / 16 warps
#define BM 128
#define BK 64
#define THREADS 512
#define ASTR 72                       // halves per A row (64 + 8 pad) -> 144 B
#define ABYTES (BM * ASTR * 2)        // 18432
#define BSTR 264                      // halves per B k-row (256 + 8 pad) -> 528 B
#define BBYTES (BK * BSTR * 2)        // 33792
#define STAGE_BYTES (ABYTES + BBYTES) // 52224
#define NSTAGES 4
#define DYN_SMEM (NSTAGES * STAGE_BYTES)   // 208896

// ---------------------------------------------------------------------------
// Static device scratch
// ---------------------------------------------------------------------------
#define GU_ROWS 9216
__device__ int    g_count[NE];
__device__ int    g_segbase[NE];
__device__ int    g_tok[NE][T];
__device__ float  g_wt[NE][T];
__device__ __align__(256) __half g_xh[(size_t)T * Hd];
__device__ __align__(256) __half g_gph[(size_t)NE * Hd * Id];
__device__ __align__(256) __half g_uph[(size_t)NE * Hd * Id];
__device__ __align__(256) __half g_dwh[(size_t)NE * Id * Hd];
__device__ __align__(256) __half g_guh[(size_t)GU_ROWS * Id];

// ---------------------------------------------------------------------------
// PTX helpers (compute_103-legal)
// ---------------------------------------------------------------------------
__device__ __forceinline__ void cp16(uint32_t dst, const void* src) {
    asm volatile("cp.async.cg.shared.global [%0], [%1], 16;" :: "r"(dst), "l"(src));
}
__device__ __forceinline__ void ldm4(uint32_t* r, uint32_t addr) {
    asm volatile("ldmatrix.sync.aligned.m8n8.x4.shared.b16 {%0,%1,%2,%3}, [%4];"
                 : "=r"(r[0]), "=r"(r[1]), "=r"(r[2]), "=r"(r[3]) : "r"(addr));
}
__device__ __forceinline__ void ldm4t(uint32_t* r, uint32_t addr) {
    asm volatile("ldmatrix.sync.aligned.m8n8.x4.trans.shared.b16 {%0,%1,%2,%3}, [%4];"
                 : "=r"(r[0]), "=r"(r[1]), "=r"(r[2]), "=r"(r[3]) : "r"(addr));
}
__device__ __forceinline__ void mma16(float* c, const uint32_t* a, uint32_t b0, uint32_t b1) {
    asm volatile("mma.sync.aligned.m16n8k16.row.col.f32.f16.f16.f32 "
        "{%0,%1,%2,%3}, {%4,%5,%6,%7}, {%8,%9}, {%0,%1,%2,%3};"
        : "+f"(c[0]), "+f"(c[1]), "+f"(c[2]), "+f"(c[3])
        : "r"(a[0]), "r"(a[1]), "r"(a[2]), "r"(a[3]), "r"(b0), "r"(b1));
}
__device__ __forceinline__ float gelu_tanh(float v) {
    const float c = 0.7978845608028654f;
    float inner = c * (v + 0.044715f * v * v * v);
    return 0.5f * v * (1.0f + tanhf(inner));
}
// Tail-correct pipeline wait: guarantee stage s is resident.
#define PIPE_WAIT(s, nst)                                                  \
    do {                                                                   \
        if ((s) + 1 >= (nst))      asm volatile("cp.async.wait_group 0;" ::: "memory"); \
        else if ((s) + 2 >= (nst)) asm volatile("cp.async.wait_group 1;" ::: "memory"); \
        else                       asm volatile("cp.async.wait_group 2;" ::: "memory"); \
    } while (0)

// ---------------------------------------------------------------------------
// fp32 -> fp16 conversion (grid-stride, float4)
// ---------------------------------------------------------------------------
__global__ void cvt_kernel(const float* __restrict__ s, __half* __restrict__ d, int n4) {
    int i = blockIdx.x * blockDim.x + threadIdx.x;
    int stride = gridDim.x * blockDim.x;
    for (; i < n4; i += stride) {
        float4 v = ((const float4*)s)[i];
        __half2 h0 = __floats2half2_rn(v.x, v.y);
        __half2 h1 = __floats2half2_rn(v.z, v.w);
        ((__half2*)d)[2 * i]     = h0;
        ((__half2*)d)[2 * i + 1] = h1;
    }
}

// ---------------------------------------------------------------------------
// Router + bookkeeping
// ---------------------------------------------------------------------------
__global__ void zero_counts_kernel() {
    if (threadIdx.x < NE) g_count[threadIdx.x] = 0;
}
__global__ void prefix_kernel() {
    if (threadIdx.x == 0) {
        int b = 0;
        for (int e = 0; e < NE; e++) {
            g_segbase[e] = b;
            b += ((g_count[e] + BM - 1) / BM) * BM;
        }
    }
}

__global__ void router_kernel(const float* __restrict__ x,
                              const float* __restrict__ gw,
                              float* __restrict__ out_logits) {
    int warp = (blockIdx.x * blockDim.x + threadIdx.x) >> 5;
    int lane = threadIdx.x & 31;
    if (warp >= T) return;
    const float* xr = x + (size_t)warp * Hd;
    float acc[NE];
#pragma unroll
    for (int e = 0; e < NE; e++) acc[e] = 0.0f;
    for (int h = lane; h < Hd; h += 32) {
        float xv = xr[h];
        const float* g = gw + (size_t)h * NE;
#pragma unroll
        for (int e = 0; e < NE; e++) acc[e] = fmaf(xv, g[e], acc[e]);
    }
#pragma unroll
    for (int e = 0; e < NE; e++) {
#pragma unroll
        for (int off = 16; off; off >>= 1)
            acc[e] += __shfl_xor_sync(0xffffffffu, acc[e], off);
    }
    if (lane == 0) {
        float* dst = out_logits + (size_t)warp * NE;
#pragma unroll
        for (int e = 0; e < NE; e++) dst[e] = acc[e];
        float l0 = -3.4e38f; int e0 = 0;
#pragma unroll
        for (int e = 0; e < NE; e++)
            if (acc[e] > l0) { l0 = acc[e]; e0 = e; }
        float l1 = -3.4e38f; int e1 = 0;
#pragma unroll
        for (int e = 0; e < NE; e++)
            if (e != e0 && acc[e] > l1) { l1 = acc[e]; e1 = e; }
        float w1 = __expf(l1 - l0);
        float inv = 1.0f / (1.0f + w1);
        int p0 = atomicAdd(&g_count[e0], 1);
        g_tok[e0][p0] = warp; g_wt[e0][p0] = inv;
        int p1 = atomicAdd(&g_count[e1], 1);
        g_tok[e1][p1] = warp; g_wt[e1][p1] = w1 * inv;
    }
}

// ---------------------------------------------------------------------------
// Gate+Up GEMM (fp16 mma.sync): per CTA 128m x (128 gate + 128 up), K=Hd.
// 16 warps: wm = wid&3 (32 rows each), wn = wid>>2 (32 gate + 32 up cols each).
// ---------------------------------------------------------------------------
__global__ __launch_bounds__(THREADS, 1)
void gateup_mma(void) {
    int e  = blockIdx.z;
    int ne = g_count[e];
    int m0 = blockIdx.x * BM;
    if (m0 >= ne) return;
    int n0 = blockIdx.y * 128;

    extern __shared__ char smem[];
    uint32_t sbase = (uint32_t)__cvta_generic_to_shared(smem);
    __shared__ int rows[BM];

    int tid = threadIdx.x;
    int lane = tid & 31, wid = tid >> 5;
    int wm = wid & 3, wn = wid >> 2;

    if (tid < BM) {
        int m = m0 + tid;
        rows[tid] = g_tok[e][m < ne ? m : (ne - 1)];
    }
    __syncthreads();

    const __half* gbh = g_gph + (size_t)e * Hd * Id + n0;
    const __half* ubh = g_uph + (size_t)e * Hd * Id + n0;

    uint32_t a_lane = sbase + (uint32_t)((wm * 32 + (lane & 15)) * (ASTR * 2) + (lane >> 4) * 16);
    uint32_t b_lane = sbase + (uint32_t)ABYTES
                    + (uint32_t)((((lane & 7) + ((lane >> 3) & 1) * 8) * (BSTR * 2)) + (lane >> 4) * 16);
    // 16 cols per ldm4t: gate pair then up pair at matching offsets
    int nmap2[4] = { wn * 32, wn * 32 + 16, 128 + wn * 32, 128 + wn * 32 + 16 };

    float c[2][8][4];
#pragma unroll
    for (int i = 0; i < 2; i++)
#pragma unroll
        for (int j = 0; j < 8; j++)
#pragma unroll
            for (int q = 0; q < 4; q++) c[i][j][q] = 0.0f;

    const int NST = Hd / BK;   // 32

    auto issue = [&](int s) {
        int k0 = s * BK;
        uint32_t a_s = sbase + (uint32_t)((s & 3) * STAGE_BYTES);
        uint32_t b_s = a_s + ABYTES;
#pragma unroll
        for (int i = 0; i < 2; i++) {              // 1024 A chunks
            int cidx = tid + i * 512;
            int m = cidx >> 3, ch = cidx & 7;
            cp16(a_s + m * (ASTR * 2) + ch * 16,
                 g_xh + (size_t)rows[m] * Hd + k0 + ch * 8);
        }
#pragma unroll
        for (int i = 0; i < 4; i++) {              // 2048 B chunks
            int cidx = tid + i * 512;
            int k = cidx >> 5, nn = (cidx & 31) * 8;
            const __half* src = (nn < 128) ? (gbh + (size_t)(k0 + k) * Id + nn)
                                           : (ubh + (size_t)(k0 + k) * Id + (nn - 128));
            cp16(b_s + k * (BSTR * 2) + nn * 2, src);
        }
        asm volatile("cp.async.commit_group;" ::: "memory");
    };

    issue(0); issue(1); issue(2);

    for (int s = 0; s < NST; s++) {
        PIPE_WAIT(s, NST);
        __syncthreads();
        if (s + 3 < NST) issue(s + 3);

        uint32_t stg = (uint32_t)((s & 3) * STAGE_BYTES);
#pragma unroll
        for (int kk = 0; kk < 4; kk++) {
            uint32_t af[2][4], bf[4][4];
#pragma unroll
            for (int i = 0; i < 2; i++)
                ldm4(af[i], a_lane + stg + (uint32_t)(i * 16 * ASTR * 2 + kk * 32));
#pragma unroll
            for (int j2 = 0; j2 < 4; j2++)
                ldm4t(bf[j2], b_lane + stg + (uint32_t)(kk * 16 * BSTR * 2 + nmap2[j2] * 2));
#pragma unroll
            for (int j = 0; j < 8; j++) {
                uint32_t b0 = bf[j >> 1][(j & 1) * 2];
                uint32_t b1 = bf[j >> 1][(j & 1) * 2 + 1];
#pragma unroll
                for (int i = 0; i < 2; i++) mma16(c[i][j], af[i], b0, b1);
            }
        }
    }

    // epilogue: gu = gelu(gate) * up -> fp16 scratch
    // j 0..3 = gate cols wn*32 + j*8 ; j+4 = up at same cols
    int seg = g_segbase[e] + m0;
#pragma unroll
    for (int i = 0; i < 2; i++) {
        int r0 = wm * 32 + i * 16 + (lane >> 2);
#pragma unroll
        for (int j = 0; j < 4; j++) {
            int nc = n0 + wn * 32 + j * 8 + (lane & 3) * 2;
            float* gg = c[i][j]; float* uu = c[i][j + 4];
            __half2 v0 = __floats2half2_rn(gelu_tanh(gg[0]) * uu[0], gelu_tanh(gg[1]) * uu[1]);
            __half2 v1 = __floats2half2_rn(gelu_tanh(gg[2]) * uu[2], gelu_tanh(gg[3]) * uu[3]);
            *(__half2*)(g_guh + (size_t)(seg + r0) * Id + nc)     = v0;
            *(__half2*)(g_guh + (size_t)(seg + r0 + 8) * Id + nc) = v1;
        }
    }
}

// ---------------------------------------------------------------------------
// Down GEMM (fp16 mma.sync): per CTA 128m x 256n, K=Id, weighted atomic scatter.
// 16 warps: wm = wid&3 (32 rows), wn = wid>>2 (64 cols).
// ---------------------------------------------------------------------------
__global__ __launch_bounds__(THREADS, 1)
void down_mma(float* __restrict__ out) {
    int e  = blockIdx.z;
    int ne = g_count[e];
    int m0 = blockIdx.x * BM;
    if (m0 >= ne) return;
    int n0 = blockIdx.y * 256;

    extern __shared__ char smem[];
    uint32_t sbase = (uint32_t)__cvta_generic_to_shared(smem);

    int tid = threadIdx.x;
    int lane = tid & 31, wid = tid >> 5;
    int wm = wid & 3, wn = wid >> 2;

    const __half* abase = g_guh + (size_t)(g_segbase[e] + m0) * Id;
    const __half* bbase = g_dwh + (size_t)e * Id * Hd + n0;

    uint32_t a_lane = sbase + (uint32_t)((wm * 32 + (lane & 15)) * (ASTR * 2) + (lane >> 4) * 16);
    uint32_t b_lane = sbase + (uint32_t)ABYTES
                    + (uint32_t)((((lane & 7) + ((lane >> 3) & 1) * 8) * (BSTR * 2)) + (lane >> 4) * 16);
    int nmap2[4] = { wn * 64, wn * 64 + 16, wn * 64 + 32, wn * 64 + 48 };

    float c[2][8][4];
#pragma unroll
    for (int i = 0; i < 2; i++)
#pragma unroll
        for (int j = 0; j < 8; j++)
#pragma unroll
            for (int q = 0; q < 4; q++) c[i][j][q] = 0.0f;

    const int NST = Id / BK;   // 64

    auto issue = [&](int s) {
        int k0 = s * BK;
        uint32_t a_s = sbase + (uint32_t)((s & 3) * STAGE_BYTES);
        uint32_t b_s = a_s + ABYTES;
#pragma unroll
        for (int i = 0; i < 2; i++) {
            int cidx = tid + i * 512;
            int m = cidx >> 3, ch = cidx & 7;
            cp16(a_s + m * (ASTR * 2) + ch * 16,
                 abase + (size_t)m * Id + k0 + ch * 8);
        }
#pragma unroll
        for (int i = 0; i < 4; i++) {
            int cidx = tid + i * 512;
            int k = cidx >> 5, nn = (cidx & 31) * 8;
            cp16(b_s + k * (BSTR * 2) + nn * 2,
                 bbase + (size_t)(k0 + k) * Hd + nn);
        }
        asm volatile("cp.async.commit_group;" ::: "memory");
    };

    issue(0); issue(1); issue(2);

    for (int s = 0; s < NST; s++) {
        PIPE_WAIT(s, NST);
        __syncthreads();
        if (s + 3 < NST) issue(s + 3);

        uint32_t stg = (uint32_t)((s & 3) * STAGE_BYTES);
#pragma unroll
        for (int kk = 0; kk < 4; kk++) {
            uint32_t af[2][4], bf[4][4];
#pragma unroll
            for (int i = 0; i < 2; i++)
                ldm4(af[i], a_lane + stg + (uint32_t)(i * 16 * ASTR * 2 + kk * 32));
#pragma unroll
            for (int j2 = 0; j2 < 4; j2++)
                ldm4t(bf[j2], b_lane + stg + (uint32_t)(kk * 16 * BSTR * 2 + nmap2[j2] * 2));
#pragma unroll
            for (int j = 0; j < 8; j++) {
                uint32_t b0 = bf[j >> 1][(j & 1) * 2];
                uint32_t b1 = bf[j >> 1][(j & 1) * 2 + 1];
#pragma unroll
                for (int i = 0; i < 2; i++) mma16(c[i][j], af[i], b0, b1);
            }
        }
    }

    // weighted scatter epilogue (cols: wn*64 + j*8)
#pragma unroll
    for (int i = 0; i < 2; i++) {
        int rl0 = m0 + wm * 32 + i * 16 + (lane >> 2);
        int rl1 = rl0 + 8;
        int   t0 = (rl0 < ne) ? g_tok[e][rl0] : -1;
        int   t1 = (rl1 < ne) ? g_tok[e][rl1] : -1;
        float w0 = (rl0 < ne) ? g_wt[e][rl0] : 0.0f;
        float w1 = (rl1 < ne) ? g_wt[e][rl1] : 0.0f;
#pragma unroll
        for (int j = 0; j < 8; j++) {
            int nc = n0 + wn * 64 + j * 8 + (lane & 3) * 2;
            if (t0 >= 0) {
                atomicAdd(out + (size_t)t0 * Hd + nc,     w0 * c[i][j][0]);
                atomicAdd(out + (size_t)t0 * Hd + nc + 1, w0 * c[i][j][1]);
            }
            if (t1 >= 0) {
                atomicAdd(out + (size_t)t1 * Hd + nc,     w1 * c[i][j][2]);
                atomicAdd(out + (size_t)t1 * Hd + nc + 1, w1 * c[i][j][3]);
            }
        }
    }
}

// ---------------------------------------------------------------------------
extern "C" void kernel_launch(void* const* d_in, const int* in_sizes, int n_in,
                              void* d_out, int out_size) {
    const float* x         = (const float*)d_in[0];
    const float* gate_w    = (const float*)d_in[1];
    const float* gate_proj = (const float*)d_in[2];
    const float* up_proj   = (const float*)d_in[3];
    const float* down_proj = (const float*)d_in[4];
    float* out = (float*)d_out;

    float* out_final  = out;
    float* out_logits = out + (size_t)T * Hd;

    cudaFuncSetAttribute(gateup_mma, cudaFuncAttributeMaxDynamicSharedMemorySize, DYN_SMEM);
    cudaFuncSetAttribute(down_mma,   cudaFuncAttributeMaxDynamicSharedMemorySize, DYN_SMEM);

    cudaMemsetAsync(out_final, 0, (size_t)T * Hd * sizeof(float));
    zero_counts_kernel<<<1, 32>>>();

    static __half *xh = nullptr, *gph = nullptr, *uph = nullptr, *dwh = nullptr;
    if (!xh) {
        cudaGetSymbolAddress((void**)&xh,  g_xh);
        cudaGetSymbolAddress((void**)&gph, g_gph);
        cudaGetSymbolAddress((void**)&uph, g_uph);
        cudaGetSymbolAddress((void**)&dwh, g_dwh);
    }
    const int WN4 = (NE * Hd * Id) / 4;
    cvt_kernel<<<4096, 256>>>(x,         xh,  (T * Hd) / 4);
    cvt_kernel<<<8192, 256>>>(gate_proj, gph, WN4);
    cvt_kernel<<<8192, 256>>>(up_proj,   uph, WN4);
    cvt_kernel<<<8192, 256>>>(down_proj, dwh, WN4);

    router_kernel<<<T / 8, 256>>>(x, gate_w, out_logits);
    prefix_kernel<<<1, 1>>>();

    dim3 g1(T / BM, Id / 128, NE);   // m fastest: B-slice L2 reuse across m-tiles
    gateup_mma<<<g1, THREADS, DYN_SMEM>>>();

    dim3 g2(T / BM, Hd / 256, NE);
    down_mma<<<g2, THREADS, DYN_SMEM>>>(out_final);
}

// round 11
// speedup vs baseline: 6.1818x; 1.1057x over previous
#include <cuda_runtime.h>
#include <cuda_fp16.h>
#include <math.h>
#include <stdint.h>

// Problem constants
#define Hd 2048
#define Id 4096
#define NE 8
#define T  4096

// GEMM tiling: CTA = 64m x 256n, BK=32 (fp16), 256 threads / 8 warps, 2 CTA/SM
#define BM 64
#define BK 32
#define THREADS 256
#define ASTR 40                       // halves per A row (32 + 8 pad) -> 80 B
#define ABYTES (BM * ASTR * 2)        // 5120
#define BSTR 264                      // halves per B k-row (256 + 8 pad) -> 528 B
#define BBYTES (BK * BSTR * 2)        // 16896
#define STAGE_BYTES (ABYTES + BBYTES) // 22016
#define NSTAGES 4
#define DYN_SMEM (NSTAGES * STAGE_BYTES)   // 88064 -> 2 CTAs/SM

// ---------------------------------------------------------------------------
// Static device scratch
// ---------------------------------------------------------------------------
#define GU_ROWS 9216
__device__ int    g_count[NE];
__device__ int    g_segbase[NE];
__device__ int    g_tok[NE][T];
__device__ float  g_wt[NE][T];
__device__ __align__(256) __half g_xh[(size_t)T * Hd];
__device__ __align__(256) __half g_gph[(size_t)NE * Hd * Id];
__device__ __align__(256) __half g_uph[(size_t)NE * Hd * Id];
__device__ __align__(256) __half g_dwh[(size_t)NE * Id * Hd];
__device__ __align__(256) __half g_guh[(size_t)GU_ROWS * Id];

// ---------------------------------------------------------------------------
// PTX helpers (compute_103-legal)
// ---------------------------------------------------------------------------
__device__ __forceinline__ void cp16(uint32_t dst, const void* src) {
    asm volatile("cp.async.cg.shared.global [%0], [%1], 16;" :: "r"(dst), "l"(src));
}
__device__ __forceinline__ void ldm4(uint32_t* r, uint32_t addr) {
    asm volatile("ldmatrix.sync.aligned.m8n8.x4.shared.b16 {%0,%1,%2,%3}, [%4];"
                 : "=r"(r[0]), "=r"(r[1]), "=r"(r[2]), "=r"(r[3]) : "r"(addr));
}
__device__ __forceinline__ void ldm4t(uint32_t* r, uint32_t addr) {
    asm volatile("ldmatrix.sync.aligned.m8n8.x4.trans.shared.b16 {%0,%1,%2,%3}, [%4];"
                 : "=r"(r[0]), "=r"(r[1]), "=r"(r[2]), "=r"(r[3]) : "r"(addr));
}
__device__ __forceinline__ void mma16(float* c, const uint32_t* a, uint32_t b0, uint32_t b1) {
    asm volatile("mma.sync.aligned.m16n8k16.row.col.f32.f16.f16.f32 "
        "{%0,%1,%2,%3}, {%4,%5,%6,%7}, {%8,%9}, {%0,%1,%2,%3};"
        : "+f"(c[0]), "+f"(c[1]), "+f"(c[2]), "+f"(c[3])
        : "r"(a[0]), "r"(a[1]), "r"(a[2]), "r"(a[3]), "r"(b0), "r"(b1));
}
__device__ __forceinline__ float gelu_tanh(float v) {
    const float c = 0.7978845608028654f;
    float inner = c * (v + 0.044715f * v * v * v);
    return 0.5f * v * (1.0f + tanhf(inner));
}
// Tail-correct pipeline wait: guarantee stage s is resident.
#define PIPE_WAIT(s, nst)                                                  \
    do {                                                                   \
        if ((s) + 1 >= (nst))      asm volatile("cp.async.wait_group 0;" ::: "memory"); \
        else if ((s) + 2 >= (nst)) asm volatile("cp.async.wait_group 1;" ::: "memory"); \
        else                       asm volatile("cp.async.wait_group 2;" ::: "memory"); \
    } while (0)

// ---------------------------------------------------------------------------
// fp32 -> fp16 conversion (grid-stride, float4)
// ---------------------------------------------------------------------------
__global__ void cvt_kernel(const float* __restrict__ s, __half* __restrict__ d, int n4) {
    int i = blockIdx.x * blockDim.x + threadIdx.x;
    int stride = gridDim.x * blockDim.x;
    for (; i < n4; i += stride) {
        float4 v = ((const float4*)s)[i];
        __half2 h0 = __floats2half2_rn(v.x, v.y);
        __half2 h1 = __floats2half2_rn(v.z, v.w);
        ((__half2*)d)[2 * i]     = h0;
        ((__half2*)d)[2 * i + 1] = h1;
    }
}

// ---------------------------------------------------------------------------
// Router + bookkeeping
// ---------------------------------------------------------------------------
__global__ void zero_counts_kernel() {
    if (threadIdx.x < NE) g_count[threadIdx.x] = 0;
}
__global__ void prefix_kernel() {
    if (threadIdx.x == 0) {
        int b = 0;
        for (int e = 0; e < NE; e++) {
            g_segbase[e] = b;
            b += ((g_count[e] + BM - 1) / BM) * BM;
        }
    }
}

__global__ void router_kernel(const float* __restrict__ x,
                              const float* __restrict__ gw,
                              float* __restrict__ out_logits) {
    int warp = (blockIdx.x * blockDim.x + threadIdx.x) >> 5;
    int lane = threadIdx.x & 31;
    if (warp >= T) return;
    const float* xr = x + (size_t)warp * Hd;
    float acc[NE];
#pragma unroll
    for (int e = 0; e < NE; e++) acc[e] = 0.0f;
    for (int h = lane; h < Hd; h += 32) {
        float xv = xr[h];
        const float* g = gw + (size_t)h * NE;
#pragma unroll
        for (int e = 0; e < NE; e++) acc[e] = fmaf(xv, g[e], acc[e]);
    }
#pragma unroll
    for (int e = 0; e < NE; e++) {
#pragma unroll
        for (int off = 16; off; off >>= 1)
            acc[e] += __shfl_xor_sync(0xffffffffu, acc[e], off);
    }
    if (lane == 0) {
        float* dst = out_logits + (size_t)warp * NE;
#pragma unroll
        for (int e = 0; e < NE; e++) dst[e] = acc[e];
        float l0 = -3.4e38f; int e0 = 0;
#pragma unroll
        for (int e = 0; e < NE; e++)
            if (acc[e] > l0) { l0 = acc[e]; e0 = e; }
        float l1 = -3.4e38f; int e1 = 0;
#pragma unroll
        for (int e = 0; e < NE; e++)
            if (e != e0 && acc[e] > l1) { l1 = acc[e]; e1 = e; }
        float w1 = __expf(l1 - l0);
        float inv = 1.0f / (1.0f + w1);
        int p0 = atomicAdd(&g_count[e0], 1);
        g_tok[e0][p0] = warp; g_wt[e0][p0] = inv;
        int p1 = atomicAdd(&g_count[e1], 1);
        g_tok[e1][p1] = warp; g_wt[e1][p1] = w1 * inv;
    }
}

// ---------------------------------------------------------------------------
// Gate+Up GEMM (fp16 mma.sync): per CTA 64m x (128 gate + 128 up), K=Hd.
// 8 warps: wm = wid&1 (32 rows), wn = wid>>1 (32 gate + 32 up cols each).
// ---------------------------------------------------------------------------
__global__ __launch_bounds__(THREADS, 2)
void gateup_mma(void) {
    int e  = blockIdx.z;
    int ne = g_count[e];
    int m0 = blockIdx.x * BM;
    if (m0 >= ne) return;
    int n0 = blockIdx.y * 128;

    extern __shared__ char smem[];
    uint32_t sbase = (uint32_t)__cvta_generic_to_shared(smem);
    __shared__ int rows[BM];

    int tid = threadIdx.x;
    int lane = tid & 31, wid = tid >> 5;
    int wm = wid & 1, wn = wid >> 1;

    if (tid < BM) {
        int m = m0 + tid;
        rows[tid] = g_tok[e][m < ne ? m : (ne - 1)];
    }
    __syncthreads();

    const __half* gbh = g_gph + (size_t)e * Hd * Id + n0;
    const __half* ubh = g_uph + (size_t)e * Hd * Id + n0;

    uint32_t a_lane = sbase + (uint32_t)((wm * 32 + (lane & 15)) * (ASTR * 2) + (lane >> 4) * 16);
    uint32_t b_lane = sbase + (uint32_t)ABYTES
                    + (uint32_t)((((lane & 7) + ((lane >> 3) & 1) * 8) * (BSTR * 2)) + (lane >> 4) * 16);
    int nmap2[4] = { wn * 32, wn * 32 + 16, 128 + wn * 32, 128 + wn * 32 + 16 };

    float c[2][8][4];
#pragma unroll
    for (int i = 0; i < 2; i++)
#pragma unroll
        for (int j = 0; j < 8; j++)
#pragma unroll
            for (int q = 0; q < 4; q++) c[i][j][q] = 0.0f;

    const int NST = Hd / BK;   // 64

    auto issue = [&](int s) {
        int k0 = s * BK;
        uint32_t a_s = sbase + (uint32_t)((s & 3) * STAGE_BYTES);
        uint32_t b_s = a_s + ABYTES;
        {   // 256 A chunks (64 rows x 4 chunks of 8 halves)
            int m = tid >> 2, ch = tid & 3;
            cp16(a_s + m * (ASTR * 2) + ch * 16,
                 g_xh + (size_t)rows[m] * Hd + k0 + ch * 8);
        }
#pragma unroll
        for (int i = 0; i < 4; i++) {              // 1024 B chunks
            int cidx = tid + i * 256;
            int k = cidx >> 5, nn = (cidx & 31) * 8;
            const __half* src = (nn < 128) ? (gbh + (size_t)(k0 + k) * Id + nn)
                                           : (ubh + (size_t)(k0 + k) * Id + (nn - 128));
            cp16(b_s + k * (BSTR * 2) + nn * 2, src);
        }
        asm volatile("cp.async.commit_group;" ::: "memory");
    };

    issue(0); issue(1); issue(2);

    for (int s = 0; s < NST; s++) {
        PIPE_WAIT(s, NST);
        __syncthreads();
        if (s + 3 < NST) issue(s + 3);

        uint32_t stg = (uint32_t)((s & 3) * STAGE_BYTES);
#pragma unroll
        for (int kk = 0; kk < 2; kk++) {
            uint32_t af[2][4], bf[4][4];
#pragma unroll
            for (int i = 0; i < 2; i++)
                ldm4(af[i], a_lane + stg + (uint32_t)(i * 16 * ASTR * 2 + kk * 32));
#pragma unroll
            for (int j2 = 0; j2 < 4; j2++)
                ldm4t(bf[j2], b_lane + stg + (uint32_t)(kk * 16 * BSTR * 2 + nmap2[j2] * 2));
#pragma unroll
            for (int j = 0; j < 8; j++) {
                uint32_t b0 = bf[j >> 1][(j & 1) * 2];
                uint32_t b1 = bf[j >> 1][(j & 1) * 2 + 1];
#pragma unroll
                for (int i = 0; i < 2; i++) mma16(c[i][j], af[i], b0, b1);
            }
        }
    }

    // epilogue: gu = gelu(gate) * up -> fp16 scratch
    int seg = g_segbase[e] + m0;
#pragma unroll
    for (int i = 0; i < 2; i++) {
        int r0 = wm * 32 + i * 16 + (lane >> 2);
#pragma unroll
        for (int j = 0; j < 4; j++) {
            int nc = n0 + wn * 32 + j * 8 + (lane & 3) * 2;
            float* gg = c[i][j]; float* uu = c[i][j + 4];
            __half2 v0 = __floats2half2_rn(gelu_tanh(gg[0]) * uu[0], gelu_tanh(gg[1]) * uu[1]);
            __half2 v1 = __floats2half2_rn(gelu_tanh(gg[2]) * uu[2], gelu_tanh(gg[3]) * uu[3]);
            *(__half2*)(g_guh + (size_t)(seg + r0) * Id + nc)     = v0;
            *(__half2*)(g_guh + (size_t)(seg + r0 + 8) * Id + nc) = v1;
        }
    }
}

// ---------------------------------------------------------------------------
// Down GEMM (fp16 mma.sync): per CTA 64m x 256n, K=Id, weighted atomic scatter.
// 8 warps: wm = wid&1 (32 rows), wn = wid>>1 (64 cols).
// ---------------------------------------------------------------------------
__global__ __launch_bounds__(THREADS, 2)
void down_mma(float* __restrict__ out) {
    int e  = blockIdx.z;
    int ne = g_count[e];
    int m0 = blockIdx.x * BM;
    if (m0 >= ne) return;
    int n0 = blockIdx.y * 256;

    extern __shared__ char smem[];
    uint32_t sbase = (uint32_t)__cvta_generic_to_shared(smem);

    int tid = threadIdx.x;
    int lane = tid & 31, wid = tid >> 5;
    int wm = wid & 1, wn = wid >> 1;

    const __half* abase = g_guh + (size_t)(g_segbase[e] + m0) * Id;
    const __half* bbase = g_dwh + (size_t)e * Id * Hd + n0;

    uint32_t a_lane = sbase + (uint32_t)((wm * 32 + (lane & 15)) * (ASTR * 2) + (lane >> 4) * 16);
    uint32_t b_lane = sbase + (uint32_t)ABYTES
                    + (uint32_t)((((lane & 7) + ((lane >> 3) & 1) * 8) * (BSTR * 2)) + (lane >> 4) * 16);
    int nmap2[4] = { wn * 64, wn * 64 + 16, wn * 64 + 32, wn * 64 + 48 };

    float c[2][8][4];
#pragma unroll
    for (int i = 0; i < 2; i++)
#pragma unroll
        for (int j = 0; j < 8; j++)
#pragma unroll
            for (int q = 0; q < 4; q++) c[i][j][q] = 0.0f;

    const int NST = Id / BK;   // 128

    auto issue = [&](int s) {
        int k0 = s * BK;
        uint32_t a_s = sbase + (uint32_t)((s & 3) * STAGE_BYTES);
        uint32_t b_s = a_s + ABYTES;
        {
            int m = tid >> 2, ch = tid & 3;
            cp16(a_s + m * (ASTR * 2) + ch * 16,
                 abase + (size_t)m * Id + k0 + ch * 8);
        }
#pragma unroll
        for (int i = 0; i < 4; i++) {
            int cidx = tid + i * 256;
            int k = cidx >> 5, nn = (cidx & 31) * 8;
            cp16(b_s + k * (BSTR * 2) + nn * 2,
                 bbase + (size_t)(k0 + k) * Hd + nn);
        }
        asm volatile("cp.async.commit_group;" ::: "memory");
    };

    issue(0); issue(1); issue(2);

    for (int s = 0; s < NST; s++) {
        PIPE_WAIT(s, NST);
        __syncthreads();
        if (s + 3 < NST) issue(s + 3);

        uint32_t stg = (uint32_t)((s & 3) * STAGE_BYTES);
#pragma unroll
        for (int kk = 0; kk < 2; kk++) {
            uint32_t af[2][4], bf[4][4];
#pragma unroll
            for (int i = 0; i < 2; i++)
                ldm4(af[i], a_lane + stg + (uint32_t)(i * 16 * ASTR * 2 + kk * 32));
#pragma unroll
            for (int j2 = 0; j2 < 4; j2++)
                ldm4t(bf[j2], b_lane + stg + (uint32_t)(kk * 16 * BSTR * 2 + nmap2[j2] * 2));
#pragma unroll
            for (int j = 0; j < 8; j++) {
                uint32_t b0 = bf[j >> 1][(j & 1) * 2];
                uint32_t b1 = bf[j >> 1][(j & 1) * 2 + 1];
#pragma unroll
                for (int i = 0; i < 2; i++) mma16(c[i][j], af[i], b0, b1);
            }
        }
    }

    // weighted scatter epilogue (cols: wn*64 + j*8)
#pragma unroll
    for (int i = 0; i < 2; i++) {
        int rl0 = m0 + wm * 32 + i * 16 + (lane >> 2);
        int rl1 = rl0 + 8;
        int   t0 = (rl0 < ne) ? g_tok[e][rl0] : -1;
        int   t1 = (rl1 < ne) ? g_tok[e][rl1] : -1;
        float w0 = (rl0 < ne) ? g_wt[e][rl0] : 0.0f;
        float w1 = (rl1 < ne) ? g_wt[e][rl1] : 0.0f;
#pragma unroll
        for (int j = 0; j < 8; j++) {
            int nc = n0 + wn * 64 + j * 8 + (lane & 3) * 2;
            if (t0 >= 0) {
                atomicAdd(out + (size_t)t0 * Hd + nc,     w0 * c[i][j][0]);
                atomicAdd(out + (size_t)t0 * Hd + nc + 1, w0 * c[i][j][1]);
            }
            if (t1 >= 0) {
                atomicAdd(out + (size_t)t1 * Hd + nc,     w1 * c[i][j][2]);
                atomicAdd(out + (size_t)t1 * Hd + nc + 1, w1 * c[i][j][3]);
            }
        }
    }
}

// ---------------------------------------------------------------------------
extern "C" void kernel_launch(void* const* d_in, const int* in_sizes, int n_in,
                              void* d_out, int out_size) {
    const float* x         = (const float*)d_in[0];
    const float* gate_w    = (const float*)d_in[1];
    const float* gate_proj = (const float*)d_in[2];
    const float* up_proj   = (const float*)d_in[3];
    const float* down_proj = (const float*)d_in[4];
    float* out = (float*)d_out;

    float* out_final  = out;
    float* out_logits = out + (size_t)T * Hd;

    cudaFuncSetAttribute(gateup_mma, cudaFuncAttributeMaxDynamicSharedMemorySize, DYN_SMEM);
    cudaFuncSetAttribute(down_mma,   cudaFuncAttributeMaxDynamicSharedMemorySize, DYN_SMEM);

    // One-time resources (created on the uncaptured correctness call; reused
    // under capture). Streams/events are not device-memory allocations.
    static __half *xh = nullptr, *gph = nullptr, *uph = nullptr, *dwh = nullptr;
    static cudaStream_t s1;
    static cudaEvent_t evFork, evGU, evDN;
    if (!xh) {
        cudaGetSymbolAddress((void**)&xh,  g_xh);
        cudaGetSymbolAddress((void**)&gph, g_gph);
        cudaGetSymbolAddress((void**)&uph, g_uph);
        cudaGetSymbolAddress((void**)&dwh, g_dwh);
        cudaStreamCreateWithFlags(&s1, cudaStreamNonBlocking);
        cudaEventCreateWithFlags(&evFork, cudaEventDisableTiming);
        cudaEventCreateWithFlags(&evGU,   cudaEventDisableTiming);
        cudaEventCreateWithFlags(&evDN,   cudaEventDisableTiming);
    }

    const int WN4 = (NE * Hd * Id) / 4;

    // Fork side stream for the conversion pass.
    cudaEventRecord(evFork, 0);
    cudaStreamWaitEvent(s1, evFork, 0);
    cvt_kernel<<<4096, 256, 0, s1>>>(x,         xh,  (T * Hd) / 4);
    cvt_kernel<<<8192, 256, 0, s1>>>(gate_proj, gph, WN4);
    cvt_kernel<<<8192, 256, 0, s1>>>(up_proj,   uph, WN4);
    cudaEventRecord(evGU, s1);
    cvt_kernel<<<8192, 256, 0, s1>>>(down_proj, dwh, WN4);
    cudaEventRecord(evDN, s1);

    // Main stream: routing while converts run.
    cudaMemsetAsync(out_final, 0, (size_t)T * Hd * sizeof(float));
    zero_counts_kernel<<<1, 32>>>();
    router_kernel<<<T / 8, 256>>>(x, gate_w, out_logits);
    prefix_kernel<<<1, 1>>>();

    cudaStreamWaitEvent(0, evGU, 0);
    dim3 g1(T / BM, Id / 128, NE);   // m fastest: B-slice L2 reuse across m-tiles
    gateup_mma<<<g1, THREADS, DYN_SMEM>>>();

    cudaStreamWaitEvent(0, evDN, 0);
    dim3 g2(T / BM, Hd / 256, NE);
    down_mma<<<g2, THREADS, DYN_SMEM>>>(out_final);
}

// round 14
// speedup vs baseline: 6.3868x; 1.0332x over previous
#include <cuda_runtime.h>
#include <cuda_fp16.h>
#include <math.h>
#include <stdint.h>

// Problem constants
#define Hd 2048
#define Id 4096
#define NE 8
#define T  4096

// GEMM tiling: CTA = 64m x 256n, BK=32 (fp16), 256 threads / 8 warps, 2 CTA/SM
#define BM 64
#define BK 32
#define THREADS 256
#define ASTR 40                       // halves per A row (32 + 8 pad) -> 80 B
#define ABYTES (BM * ASTR * 2)        // 5120
#define BSTR 264                      // halves per B k-row (256 + 8 pad) -> 528 B
#define BBYTES (BK * BSTR * 2)        // 16896
#define STAGE_BYTES (ABYTES + BBYTES) // 22016
#define NSTAGES 5
#define DYN_SMEM (NSTAGES * STAGE_BYTES)   // 110080 -> still 2 CTAs/SM

// ---------------------------------------------------------------------------
// Static device scratch
// ---------------------------------------------------------------------------
#define GU_ROWS 9216
__device__ int    g_count[NE];
__device__ int    g_segbase[NE];
__device__ int    g_tok[NE][T];
__device__ int    g_sE[T * 2];
__device__ int    g_sP[T * 2];
__device__ float  g_sW[T * 2];
__device__ __align__(256) __half g_xh[(size_t)T * Hd];
__device__ __align__(256) __half g_gph[(size_t)NE * Hd * Id];
__device__ __align__(256) __half g_uph[(size_t)NE * Hd * Id];
__device__ __align__(256) __half g_dwh[(size_t)NE * Id * Hd];
__device__ __align__(256) __half g_guh[(size_t)GU_ROWS * Id];
__device__ __align__(256) float  g_scr[(size_t)GU_ROWS * Hd];

// ---------------------------------------------------------------------------
// PTX helpers (compute_103-legal)
// ---------------------------------------------------------------------------
__device__ __forceinline__ void cp16(uint32_t dst, const void* src) {
    asm volatile("cp.async.cg.shared.global [%0], [%1], 16;" :: "r"(dst), "l"(src));
}
__device__ __forceinline__ void ldm4(uint32_t* r, uint32_t addr) {
    asm volatile("ldmatrix.sync.aligned.m8n8.x4.shared.b16 {%0,%1,%2,%3}, [%4];"
                 : "=r"(r[0]), "=r"(r[1]), "=r"(r[2]), "=r"(r[3]) : "r"(addr));
}
__device__ __forceinline__ void ldm4t(uint32_t* r, uint32_t addr) {
    asm volatile("ldmatrix.sync.aligned.m8n8.x4.trans.shared.b16 {%0,%1,%2,%3}, [%4];"
                 : "=r"(r[0]), "=r"(r[1]), "=r"(r[2]), "=r"(r[3]) : "r"(addr));
}
__device__ __forceinline__ void mma16(float* c, const uint32_t* a, uint32_t b0, uint32_t b1) {
    asm volatile("mma.sync.aligned.m16n8k16.row.col.f32.f16.f16.f32 "
        "{%0,%1,%2,%3}, {%4,%5,%6,%7}, {%8,%9}, {%0,%1,%2,%3};"
        : "+f"(c[0]), "+f"(c[1]), "+f"(c[2]), "+f"(c[3])
        : "r"(a[0]), "r"(a[1]), "r"(a[2]), "r"(a[3]), "r"(b0), "r"(b1));
}
__device__ __forceinline__ float gelu_tanh(float v) {
    const float c = 0.7978845608028654f;
    float inner = c * (v + 0.044715f * v * v * v);
    return 0.5f * v * (1.0f + tanhf(inner));
}
// Pipeline wait: guarantee stage s resident given groups 0..min(s+3, nst-1) issued.
#define PIPE_WAIT(s, nst)                                                   \
    do {                                                                    \
        int rem = (nst) - 1 - (s);                                          \
        if (rem >= 3)      asm volatile("cp.async.wait_group 3;" ::: "memory"); \
        else if (rem == 2) asm volatile("cp.async.wait_group 2;" ::: "memory"); \
        else if (rem == 1) asm volatile("cp.async.wait_group 1;" ::: "memory"); \
        else               asm volatile("cp.async.wait_group 0;" ::: "memory"); \
    } while (0)

// ---------------------------------------------------------------------------
// fp32 -> fp16 conversion (grid-stride, float4)
// ---------------------------------------------------------------------------
__global__ void cvt_kernel(const float* __restrict__ s, __half* __restrict__ d, int n4) {
    int i = blockIdx.x * blockDim.x + threadIdx.x;
    int stride = gridDim.x * blockDim.x;
    for (; i < n4; i += stride) {
        float4 v = ((const float4*)s)[i];
        __half2 h0 = __floats2half2_rn(v.x, v.y);
        __half2 h1 = __floats2half2_rn(v.z, v.w);
        ((__half2*)d)[2 * i]     = h0;
        ((__half2*)d)[2 * i + 1] = h1;
    }
}

// ---------------------------------------------------------------------------
// Router + bookkeeping
// ---------------------------------------------------------------------------
__global__ void zero_counts_kernel() {
    if (threadIdx.x < NE) g_count[threadIdx.x] = 0;
}
__global__ void prefix_kernel() {
    if (threadIdx.x == 0) {
        int b = 0;
        for (int e = 0; e < NE; e++) {
            g_segbase[e] = b;
            b += ((g_count[e] + BM - 1) / BM) * BM;
        }
    }
}

__global__ void router_kernel(const float* __restrict__ x,
                              const float* __restrict__ gw,
                              float* __restrict__ out_logits) {
    int warp = (blockIdx.x * blockDim.x + threadIdx.x) >> 5;
    int lane = threadIdx.x & 31;
    if (warp >= T) return;
    const float* xr = x + (size_t)warp * Hd;
    float acc[NE];
#pragma unroll
    for (int e = 0; e < NE; e++) acc[e] = 0.0f;
    for (int h = lane; h < Hd; h += 32) {
        float xv = xr[h];
        const float* g = gw + (size_t)h * NE;
#pragma unroll
        for (int e = 0; e < NE; e++) acc[e] = fmaf(xv, g[e], acc[e]);
    }
#pragma unroll
    for (int e = 0; e < NE; e++) {
#pragma unroll
        for (int off = 16; off; off >>= 1)
            acc[e] += __shfl_xor_sync(0xffffffffu, acc[e], off);
    }
    if (lane == 0) {
        float* dst = out_logits + (size_t)warp * NE;
#pragma unroll
        for (int e = 0; e < NE; e++) dst[e] = acc[e];
        float l0 = -3.4e38f; int e0 = 0;
#pragma unroll
        for (int e = 0; e < NE; e++)
            if (acc[e] > l0) { l0 = acc[e]; e0 = e; }
        float l1 = -3.4e38f; int e1 = 0;
#pragma unroll
        for (int e = 0; e < NE; e++)
            if (e != e0 && acc[e] > l1) { l1 = acc[e]; e1 = e; }
        float w1 = __expf(l1 - l0);
        float inv = 1.0f / (1.0f + w1);
        int p0 = atomicAdd(&g_count[e0], 1);
        g_tok[e0][p0] = warp;
        g_sE[2 * warp] = e0; g_sP[2 * warp] = p0; g_sW[2 * warp] = inv;
        int p1 = atomicAdd(&g_count[e1], 1);
        g_tok[e1][p1] = warp;
        g_sE[2 * warp + 1] = e1; g_sP[2 * warp + 1] = p1; g_sW[2 * warp + 1] = w1 * inv;
    }
}

// ---------------------------------------------------------------------------
// Gate+Up GEMM (fp16 mma.sync): per CTA 64m x (128 gate + 128 up), K=Hd.
// ---------------------------------------------------------------------------
__global__ __launch_bounds__(THREADS, 2)
void gateup_mma(void) {
    int e  = blockIdx.z;
    int ne = g_count[e];
    int m0 = blockIdx.x * BM;
    if (m0 >= ne) return;
    int n0 = blockIdx.y * 128;

    extern __shared__ char smem[];
    uint32_t sbase = (uint32_t)__cvta_generic_to_shared(smem);
    __shared__ int rows[BM];

    int tid = threadIdx.x;
    int lane = tid & 31, wid = tid >> 5;
    int wm = wid & 1, wn = wid >> 1;

    if (tid < BM) {
        int m = m0 + tid;
        rows[tid] = g_tok[e][m < ne ? m : (ne - 1)];
    }
    __syncthreads();

    const __half* gbh = g_gph + (size_t)e * Hd * Id + n0;
    const __half* ubh = g_uph + (size_t)e * Hd * Id + n0;

    uint32_t a_lane = sbase + (uint32_t)((wm * 32 + (lane & 15)) * (ASTR * 2) + (lane >> 4) * 16);
    uint32_t b_lane = sbase + (uint32_t)ABYTES
                    + (uint32_t)((((lane & 7) + ((lane >> 3) & 1) * 8) * (BSTR * 2)) + (lane >> 4) * 16);
    int nmap2[4] = { wn * 32, wn * 32 + 16, 128 + wn * 32, 128 + wn * 32 + 16 };

    float c[2][8][4];
#pragma unroll
    for (int i = 0; i < 2; i++)
#pragma unroll
        for (int j = 0; j < 8; j++)
#pragma unroll
            for (int q = 0; q < 4; q++) c[i][j][q] = 0.0f;

    const int NST = Hd / BK;   // 64

    auto issue = [&](int s) {
        int k0 = s * BK;
        uint32_t a_s = sbase + (uint32_t)((s % NSTAGES) * STAGE_BYTES);
        uint32_t b_s = a_s + ABYTES;
        {
            int m = tid >> 2, ch = tid & 3;
            cp16(a_s + m * (ASTR * 2) + ch * 16,
                 g_xh + (size_t)rows[m] * Hd + k0 + ch * 8);
        }
#pragma unroll
        for (int i = 0; i < 4; i++) {
            int cidx = tid + i * 256;
            int k = cidx >> 5, nn = (cidx & 31) * 8;
            const __half* src = (nn < 128) ? (gbh + (size_t)(k0 + k) * Id + nn)
                                           : (ubh + (size_t)(k0 + k) * Id + (nn - 128));
            cp16(b_s + k * (BSTR * 2) + nn * 2, src);
        }
        asm volatile("cp.async.commit_group;" ::: "memory");
    };

    issue(0); issue(1); issue(2); issue(3);

    for (int s = 0; s < NST; s++) {
        PIPE_WAIT(s, NST);
        __syncthreads();
        if (s + 4 < NST) issue(s + 4);

        uint32_t stg = (uint32_t)((s % NSTAGES) * STAGE_BYTES);
#pragma unroll
        for (int kk = 0; kk < 2; kk++) {
            uint32_t af[2][4], bf[4][4];
#pragma unroll
            for (int i = 0; i < 2; i++)
                ldm4(af[i], a_lane + stg + (uint32_t)(i * 16 * ASTR * 2 + kk * 32));
#pragma unroll
            for (int j2 = 0; j2 < 4; j2++)
                ldm4t(bf[j2], b_lane + stg + (uint32_t)(kk * 16 * BSTR * 2 + nmap2[j2] * 2));
#pragma unroll
            for (int j = 0; j < 8; j++) {
                uint32_t b0 = bf[j >> 1][(j & 1) * 2];
                uint32_t b1 = bf[j >> 1][(j & 1) * 2 + 1];
#pragma unroll
                for (int i = 0; i < 2; i++) mma16(c[i][j], af[i], b0, b1);
            }
        }
    }

    // epilogue: gu = gelu(gate) * up -> fp16 scratch
    int seg = g_segbase[e] + m0;
#pragma unroll
    for (int i = 0; i < 2; i++) {
        int r0 = wm * 32 + i * 16 + (lane >> 2);
#pragma unroll
        for (int j = 0; j < 4; j++) {
            int nc = n0 + wn * 32 + j * 8 + (lane & 3) * 2;
            float* gg = c[i][j]; float* uu = c[i][j + 4];
            __half2 v0 = __floats2half2_rn(gelu_tanh(gg[0]) * uu[0], gelu_tanh(gg[1]) * uu[1]);
            __half2 v1 = __floats2half2_rn(gelu_tanh(gg[2]) * uu[2], gelu_tanh(gg[3]) * uu[3]);
            *(__half2*)(g_guh + (size_t)(seg + r0) * Id + nc)     = v0;
            *(__half2*)(g_guh + (size_t)(seg + r0 + 8) * Id + nc) = v1;
        }
    }
}

// ---------------------------------------------------------------------------
// Down GEMM (fp16 mma.sync): per CTA 64m x 256n, K=Id.
// Writes raw per-slot results to g_scr (no atomics; weights applied in combine).
// ---------------------------------------------------------------------------
__global__ __launch_bounds__(THREADS, 2)
void down_mma(void) {
    int e  = blockIdx.z;
    int ne = g_count[e];
    int m0 = blockIdx.x * BM;
    if (m0 >= ne) return;
    int n0 = blockIdx.y * 256;

    extern __shared__ char smem[];
    uint32_t sbase = (uint32_t)__cvta_generic_to_shared(smem);

    int tid = threadIdx.x;
    int lane = tid & 31, wid = tid >> 5;
    int wm = wid & 1, wn = wid >> 1;

    int seg = g_segbase[e] + m0;
    const __half* abase = g_guh + (size_t)seg * Id;
    const __half* bbase = g_dwh + (size_t)e * Id * Hd + n0;

    uint32_t a_lane = sbase + (uint32_t)((wm * 32 + (lane & 15)) * (ASTR * 2) + (lane >> 4) * 16);
    uint32_t b_lane = sbase + (uint32_t)ABYTES
                    + (uint32_t)((((lane & 7) + ((lane >> 3) & 1) * 8) * (BSTR * 2)) + (lane >> 4) * 16);
    int nmap2[4] = { wn * 64, wn * 64 + 16, wn * 64 + 32, wn * 64 + 48 };

    float c[2][8][4];
#pragma unroll
    for (int i = 0; i < 2; i++)
#pragma unroll
        for (int j = 0; j < 8; j++)
#pragma unroll
            for (int q = 0; q < 4; q++) c[i][j][q] = 0.0f;

    const int NST = Id / BK;   // 128

    auto issue = [&](int s) {
        int k0 = s * BK;
        uint32_t a_s = sbase + (uint32_t)((s % NSTAGES) * STAGE_BYTES);
        uint32_t b_s = a_s + ABYTES;
        {
            int m = tid >> 2, ch = tid & 3;
            cp16(a_s + m * (ASTR * 2) + ch * 16,
                 abase + (size_t)m * Id + k0 + ch * 8);
        }
#pragma unroll
        for (int i = 0; i < 4; i++) {
            int cidx = tid + i * 256;
            int k = cidx >> 5, nn = (cidx & 31) * 8;
            cp16(b_s + k * (BSTR * 2) + nn * 2,
                 bbase + (size_t)(k0 + k) * Hd + nn);
        }
        asm volatile("cp.async.commit_group;" ::: "memory");
    };

    issue(0); issue(1); issue(2); issue(3);

    for (int s = 0; s < NST; s++) {
        PIPE_WAIT(s, NST);
        __syncthreads();
        if (s + 4 < NST) issue(s + 4);

        uint32_t stg = (uint32_t)((s % NSTAGES) * STAGE_BYTES);
#pragma unroll
        for (int kk = 0; kk < 2; kk++) {
            uint32_t af[2][4], bf[4][4];
#pragma unroll
            for (int i = 0; i < 2; i++)
                ldm4(af[i], a_lane + stg + (uint32_t)(i * 16 * ASTR * 2 + kk * 32));
#pragma unroll
            for (int j2 = 0; j2 < 4; j2++)
                ldm4t(bf[j2], b_lane + stg + (uint32_t)(kk * 16 * BSTR * 2 + nmap2[j2] * 2));
#pragma unroll
            for (int j = 0; j < 8; j++) {
                uint32_t b0 = bf[j >> 1][(j & 1) * 2];
                uint32_t b1 = bf[j >> 1][(j & 1) * 2 + 1];
#pragma unroll
                for (int i = 0; i < 2; i++) mma16(c[i][j], af[i], b0, b1);
            }
        }
    }

    // raw store epilogue (pad rows written harmlessly; combine never reads them)
#pragma unroll
    for (int i = 0; i < 2; i++) {
        int r0 = seg + wm * 32 + i * 16 + (lane >> 2);
#pragma unroll
        for (int j = 0; j < 8; j++) {
            int nc = n0 + wn * 64 + j * 8 + (lane & 3) * 2;
            *(float2*)(g_scr + (size_t)r0 * Hd + nc)       = make_float2(c[i][j][0], c[i][j][1]);
            *(float2*)(g_scr + (size_t)(r0 + 8) * Hd + nc) = make_float2(c[i][j][2], c[i][j][3]);
        }
    }
}

// ---------------------------------------------------------------------------
// Combine: out[t] = w0 * scr[slot0(t)] + w1 * scr[slot1(t)]
// ---------------------------------------------------------------------------
__global__ void combine_kernel(float* __restrict__ out) {
    int i = blockIdx.x * blockDim.x + threadIdx.x;   // T * Hd/4 threads
    int t  = i >> 9;            // Hd/4 = 512
    int c4 = i & 511;
    int r0 = g_segbase[g_sE[2 * t]]     + g_sP[2 * t];
    int r1 = g_segbase[g_sE[2 * t + 1]] + g_sP[2 * t + 1];
    float w0 = g_sW[2 * t], w1 = g_sW[2 * t + 1];
    float4 a = ((const float4*)g_scr)[(size_t)r0 * 512 + c4];
    float4 b = ((const float4*)g_scr)[(size_t)r1 * 512 + c4];
    float4 o;
    o.x = w0 * a.x + w1 * b.x;
    o.y = w0 * a.y + w1 * b.y;
    o.z = w0 * a.z + w1 * b.z;
    o.w = w0 * a.w + w1 * b.w;
    ((float4*)out)[i] = o;
}

// ---------------------------------------------------------------------------
extern "C" void kernel_launch(void* const* d_in, const int* in_sizes, int n_in,
                              void* d_out, int out_size) {
    const float* x         = (const float*)d_in[0];
    const float* gate_w    = (const float*)d_in[1];
    const float* gate_proj = (const float*)d_in[2];
    const float* up_proj   = (const float*)d_in[3];
    const float* down_proj = (const float*)d_in[4];
    float* out = (float*)d_out;

    float* out_final  = out;
    float* out_logits = out + (size_t)T * Hd;

    cudaFuncSetAttribute(gateup_mma, cudaFuncAttributeMaxDynamicSharedMemorySize, DYN_SMEM);
    cudaFuncSetAttribute(down_mma,   cudaFuncAttributeMaxDynamicSharedMemorySize, DYN_SMEM);

    // One-time resources — EXACTLY the Round-11 footprint that passed the
    // allocation guard (1 stream + 4 events; created on the uncaptured
    // correctness call, reused under capture).
    static __half *xh = nullptr, *gph = nullptr, *uph = nullptr, *dwh = nullptr;
    static cudaStream_t s1;
    static cudaEvent_t evFork, evGU, evDN;
    if (!xh) {
        cudaGetSymbolAddress((void**)&xh,  g_xh);
        cudaGetSymbolAddress((void**)&gph, g_gph);
        cudaGetSymbolAddress((void**)&uph, g_uph);
        cudaGetSymbolAddress((void**)&dwh, g_dwh);
        cudaStreamCreateWithFlags(&s1, cudaStreamNonBlocking);
        cudaEventCreateWithFlags(&evFork, cudaEventDisableTiming);
        cudaEventCreateWithFlags(&evGU,   cudaEventDisableTiming);
        cudaEventCreateWithFlags(&evDN,   cudaEventDisableTiming);
    }

    const int WN4 = (NE * Hd * Id) / 4;

    // Fork side stream for the conversion pass.
    cudaEventRecord(evFork, 0);
    cudaStreamWaitEvent(s1, evFork, 0);
    cvt_kernel<<<4096, 256, 0, s1>>>(x,         xh,  (T * Hd) / 4);
    cvt_kernel<<<8192, 256, 0, s1>>>(gate_proj, gph, WN4);
    cvt_kernel<<<8192, 256, 0, s1>>>(up_proj,   uph, WN4);
    cudaEventRecord(evGU, s1);
    cvt_kernel<<<8192, 256, 0, s1>>>(down_proj, dwh, WN4);
    cudaEventRecord(evDN, s1);

    // Main stream: routing while converts run (no output memset needed —
    // combine_kernel writes every output element).
    zero_counts_kernel<<<1, 32>>>();
    router_kernel<<<T / 8, 256>>>(x, gate_w, out_logits);
    prefix_kernel<<<1, 1>>>();

    cudaStreamWaitEvent(0, evGU, 0);
    dim3 g1(T / BM, Id / 128, NE);   // m fastest: B-slice L2 reuse across m-tiles
    gateup_mma<<<g1, THREADS, DYN_SMEM>>>();

    cudaStreamWaitEvent(0, evDN, 0);
    dim3 g2(T / BM, Hd / 256, NE);
    down_mma<<<g2, THREADS, DYN_SMEM>>>();

    combine_kernel<<<(T * Hd / 4) / 256, 256>>>(out_final);
}